// round 2
// baseline (speedup 1.0000x reference)
#include <cuda_runtime.h>

// ---------------------------------------------------------------------------
// GIN (2 layers) on GB300.
//   h1pre = x + scatter_sum(x[src] -> dst)            [N,64]
//   t1    = relu(h1pre @ W1 + b1)                     [N,128]
//   h     = relu(t1    @ W2 + b2)                     [N,128]
//   h2pre = h + scatter_sum(h[src] -> dst)            [N,128]
//   t2    = relu(h2pre @ W3 + b3)                     [N,128]
//   out   = t2 @ W4 + b4                              [N,64]
//
// NOTE: edge_index dtype is ambiguous (JAX x64 default-off makes jnp.int64
// silently int32). A device-side detection kernel sets g_is64 once per launch.
// ---------------------------------------------------------------------------

#define NMAX 50000
#define CIN  64
#define CHID 128

__device__ float g_h1pre[NMAX * CIN];
__device__ float g_t1   [NMAX * CHID];
__device__ float g_h    [NMAX * CHID];
__device__ float g_h2pre[NMAX * CHID];
__device__ float g_t2   [NMAX * CHID];
__device__ unsigned g_is64;

// ---------------------------------------------------------------------------
// Detect whether the index buffer is int64 (high words all zero) or int32.
__global__ void detect_idx_kernel(const unsigned* __restrict__ ei_u32) {
    if (threadIdx.x == 0 && blockIdx.x == 0) {
        unsigned acc = 0;
#pragma unroll 8
        for (int i = 0; i < 512; ++i) acc |= ei_u32[2 * i + 1];
        g_is64 = (acc == 0u) ? 1u : 0u;
    }
}

// ---------------------------------------------------------------------------
__global__ void copy_kernel(const float4* __restrict__ src, float4* __restrict__ dst, int n4) {
    int i = blockIdx.x * blockDim.x + threadIdx.x;
    if (i < n4) dst[i] = src[i];
}

// One warp per edge. Lane 0 loads (src,dst) with dtype decided by g_is64,
// broadcast via shfl, then lanes move C channels with vector loads + fp32
// atomic adds (no return use -> REDG).
template <int C>
__global__ void scatter_add_kernel(const float* __restrict__ feat,
                                   const void* __restrict__ ei,
                                   float* __restrict__ out, int E) {
    int gw   = (int)((blockIdx.x * blockDim.x + threadIdx.x) >> 5);
    int lane = threadIdx.x & 31;
    if (gw >= E) return;
    long long sd = 0;  // packed: s in low 32 (as value), d in high via two ints
    int s = 0, d = 0;
    if (lane == 0) {
        if (g_is64) {
            const long long* p = (const long long*)ei;
            s = (int)p[gw];
            d = (int)p[gw + E];
        } else {
            const int* p = (const int*)ei;
            s = p[gw];
            d = p[gw + E];
        }
        sd = ((long long)d << 32) | (unsigned)s;
    }
    sd = __shfl_sync(0xffffffffu, sd, 0);
    s = (int)(sd & 0xffffffff);
    d = (int)(sd >> 32);
    const float* fs = feat + (long long)s * C;
    float*       fo = out  + (long long)d * C;
    if (C == 64) {
        float2 v = ((const float2*)fs)[lane];
        atomicAdd(&fo[lane * 2 + 0], v.x);
        atomicAdd(&fo[lane * 2 + 1], v.y);
    } else {
        float4 v = ((const float4*)fs)[lane];
        atomicAdd(&fo[lane * 4 + 0], v.x);
        atomicAdd(&fo[lane * 4 + 1], v.y);
        atomicAdd(&fo[lane * 4 + 2], v.z);
        atomicAdd(&fo[lane * 4 + 3], v.w);
    }
}

// ---------------------------------------------------------------------------
// Fused GEMM + bias (+ optional ReLU):  C[N,CO] = act(A[N,CI] @ W[CI,CO] + b)
// BM=128 rows per block, BN=CO (64 or 128), BK=32, 256 threads, TMxTN microtiles.
template <int CI, int CO, int RELU>
__launch_bounds__(256)
__global__ void gemm_bias_kernel(const float* __restrict__ A,
                                 const float* __restrict__ W,
                                 const float* __restrict__ bias,
                                 float* __restrict__ Cmat, int Nrows) {
    constexpr int BM = 128;
    constexpr int BK = 32;
    constexpr int BN = CO;          // 64 or 128
    constexpr int TM = 8;
    constexpr int TN = BN / 16;     // 8 (CO=128) or 4 (CO=64)

    __shared__ float As[BK][BM + 1];   // +1 pad: conflict-free transposed stores
    __shared__ float Bs[BK][BN];       // rows 16B-aligned

    const int tid = threadIdx.x;                 // 0..255
    const int tr  = tid >> 4;                    // 0..15 (row group)
    const int tc  = tid & 15;                    // 0..15 (col group)
    const long long rowBase = (long long)blockIdx.x * BM;

    float acc[TM][TN];
#pragma unroll
    for (int i = 0; i < TM; ++i)
#pragma unroll
        for (int j = 0; j < TN; ++j) acc[i][j] = 0.f;

    for (int k0 = 0; k0 < CI; k0 += BK) {
        // --- load A tile (BM x BK), transposed into smem ---
#pragma unroll
        for (int it = 0; it < (BM * BK) / (256 * 4); ++it) {
            int idx = tid + it * 256;          // one float4 each
            int m   = idx >> 3;                // BK/4 = 8 float4 per row
            int kq  = idx & 7;
            long long row = rowBase + m;
            float4 v = make_float4(0.f, 0.f, 0.f, 0.f);
            if (row < Nrows)
                v = ((const float4*)(A + row * CI + k0))[kq];
            As[kq * 4 + 0][m] = v.x;
            As[kq * 4 + 1][m] = v.y;
            As[kq * 4 + 2][m] = v.z;
            As[kq * 4 + 3][m] = v.w;
        }
        // --- load W tile (BK x BN) ---
#pragma unroll
        for (int it = 0; it < (BK * BN) / (256 * 4); ++it) {
            int idx = tid + it * 256;
            int k   = idx / (BN / 4);
            int nq  = idx % (BN / 4);
            float4 v = ((const float4*)(W + (long long)(k0 + k) * CO))[nq];
            *((float4*)&Bs[k][nq * 4]) = v;
        }
        __syncthreads();

#pragma unroll
        for (int k = 0; k < BK; ++k) {
            float a[TM], b[TN];
#pragma unroll
            for (int i = 0; i < TM; ++i) a[i] = As[k][tr * TM + i];
#pragma unroll
            for (int j = 0; j < TN; ++j) b[j] = Bs[k][tc * TN + j];
#pragma unroll
            for (int i = 0; i < TM; ++i)
#pragma unroll
                for (int j = 0; j < TN; ++j) acc[i][j] += a[i] * b[j];
        }
        __syncthreads();
    }

    // --- epilogue: bias (+relu) + store ---
#pragma unroll
    for (int i = 0; i < TM; ++i) {
        long long row = rowBase + tr * TM + i;
        if (row >= Nrows) continue;
#pragma unroll
        for (int j = 0; j < TN; ++j) {
            int n = tc * TN + j;
            float c = acc[i][j] + bias[n];
            if (RELU) c = fmaxf(c, 0.f);
            Cmat[row * CO + n] = c;
        }
    }
}

// ---------------------------------------------------------------------------
extern "C" void kernel_launch(void* const* d_in, const int* in_sizes, int n_in,
                              void* d_out, int out_size) {
    const float* x  = (const float*)d_in[0];
    const void*  ei = d_in[1];
    const float* W1 = (const float*)d_in[2];
    const float* b1 = (const float*)d_in[3];
    const float* W2 = (const float*)d_in[4];
    const float* b2 = (const float*)d_in[5];
    const float* W3 = (const float*)d_in[6];
    const float* b3 = (const float*)d_in[7];
    const float* W4 = (const float*)d_in[8];
    const float* b4 = (const float*)d_in[9];

    const int N = in_sizes[0] / CIN;
    const int E = in_sizes[1] / 2;

    float *h1pre, *t1, *h, *h2pre, *t2;
    cudaGetSymbolAddress((void**)&h1pre, g_h1pre);
    cudaGetSymbolAddress((void**)&t1,    g_t1);
    cudaGetSymbolAddress((void**)&h,     g_h);
    cudaGetSymbolAddress((void**)&h2pre, g_h2pre);
    cudaGetSymbolAddress((void**)&t2,    g_t2);

    float* out = (float*)d_out;
    const int gemm_blocks = (N + 127) / 128;
    const int scat_blocks = (E + 7) / 8;   // 8 warps/block, 1 warp/edge

    detect_idx_kernel<<<1, 32>>>((const unsigned*)ei);

    // ---- Layer 1 ----
    {
        int n4 = N * CIN / 4;
        copy_kernel<<<(n4 + 255) / 256, 256>>>((const float4*)x, (float4*)h1pre, n4);
    }
    scatter_add_kernel<CIN><<<scat_blocks, 256>>>(x, ei, h1pre, E);
    gemm_bias_kernel<CIN,  CHID, 1><<<gemm_blocks, 256>>>(h1pre, W1, b1, t1, N);
    gemm_bias_kernel<CHID, CHID, 1><<<gemm_blocks, 256>>>(t1,    W2, b2, h,  N);

    // ---- Layer 2 ----
    {
        int n4 = N * CHID / 4;
        copy_kernel<<<(n4 + 255) / 256, 256>>>((const float4*)h, (float4*)h2pre, n4);
    }
    scatter_add_kernel<CHID><<<scat_blocks, 256>>>(h, ei, h2pre, E);
    gemm_bias_kernel<CHID, CHID, 1><<<gemm_blocks, 256>>>(h2pre, W3, b3, t2,  N);
    gemm_bias_kernel<CHID, CIN,  0><<<gemm_blocks, 256>>>(t2,    W4, b4, out, N);
}

// round 3
// speedup vs baseline: 1.4215x; 1.4215x over previous
#include <cuda_runtime.h>

// ---------------------------------------------------------------------------
// GIN (2 layers) on GB300 — CSR-gather aggregation + register-tiled SGEMMs.
//   CSR build (once per launch):  deg histogram -> scan -> fill
//   h1pre = x + gather_sum(x, CSR)                    [N,64]
//   t1    = relu(h1pre @ W1 + b1)                     [N,128]
//   h     = relu(t1    @ W2 + b2)                     [N,128]
//   h2pre = h + gather_sum(h, CSR)                    [N,128]
//   t2    = relu(h2pre @ W3 + b3)                     [N,128]
//   out   = t2 @ W4 + b4                              [N,64]
// edge_index dtype (int32 vs int64) detected on-device (g_is64).
// ---------------------------------------------------------------------------

#define NMAX 50000
#define EMAX 800000
#define CIN  64
#define CHID 128

__device__ float g_h1pre[NMAX * CIN];
__device__ float g_t1   [NMAX * CHID];
__device__ float g_h    [NMAX * CHID];
__device__ float g_h2pre[NMAX * CHID];
__device__ float g_t2   [NMAX * CHID];

__device__ int g_deg   [NMAX];
__device__ int g_offs  [NMAX + 1];
__device__ int g_cursor[NMAX];
__device__ int g_csr   [EMAX];
__device__ unsigned g_is64;

// ---------------------------------------------------------------------------
__global__ void detect_idx_kernel(const unsigned* __restrict__ ei_u32) {
    if (threadIdx.x == 0 && blockIdx.x == 0) {
        unsigned acc = 0;
#pragma unroll 8
        for (int i = 0; i < 512; ++i) acc |= ei_u32[2 * i + 1];
        g_is64 = (acc == 0u) ? 1u : 0u;
    }
}

__global__ void zero_kernel(int* __restrict__ p, int n) {
    int i = blockIdx.x * blockDim.x + threadIdx.x;
    if (i < n) p[i] = 0;
}

__global__ void hist_kernel(const void* __restrict__ ei, int* __restrict__ deg, int E) {
    int e = blockIdx.x * blockDim.x + threadIdx.x;
    if (e >= E) return;
    int d = g_is64 ? (int)((const long long*)ei)[E + e] : ((const int*)ei)[E + e];
    atomicAdd(&deg[d], 1);
}

// Single-block exclusive scan of deg[0..N) -> offs / cursor; offs[N] = total.
__global__ void scan_kernel(const int* __restrict__ deg, int* __restrict__ offs,
                            int* __restrict__ cursor, int N) {
    __shared__ int wsum[32];
    __shared__ int sbcarry;
    const int tid = threadIdx.x, lane = tid & 31, wid = tid >> 5;
    if (tid == 0) sbcarry = 0;
    __syncthreads();
    for (int base = 0; base < N; base += 1024) {
        int i = base + tid;
        int v = (i < N) ? deg[i] : 0;
        int x = v;
#pragma unroll
        for (int o = 1; o < 32; o <<= 1) {
            int y = __shfl_up_sync(0xffffffffu, x, o);
            if (lane >= o) x += y;
        }
        if (lane == 31) wsum[wid] = x;
        __syncthreads();
        if (wid == 0) {
            int w = wsum[lane];
#pragma unroll
            for (int o = 1; o < 32; o <<= 1) {
                int y = __shfl_up_sync(0xffffffffu, w, o);
                if (lane >= o) w += y;
            }
            wsum[lane] = w;
        }
        __syncthreads();
        int warpoff = (wid > 0) ? wsum[wid - 1] : 0;
        int excl = sbcarry + warpoff + x - v;
        if (i < N) { offs[i] = excl; cursor[i] = excl; }
        int btotal = wsum[31];
        __syncthreads();
        if (tid == 0) sbcarry += btotal;
        __syncthreads();
    }
    if (tid == 0) offs[N] = sbcarry;
}

__global__ void fill_kernel(const void* __restrict__ ei, int* __restrict__ cursor,
                            int* __restrict__ csr, int E) {
    int e = blockIdx.x * blockDim.x + threadIdx.x;
    if (e >= E) return;
    int s, d;
    if (g_is64) {
        const long long* p = (const long long*)ei;
        s = (int)p[e];
        d = (int)p[E + e];
    } else {
        const int* p = (const int*)ei;
        s = p[e];
        d = p[E + e];
    }
    int pos = atomicAdd(&cursor[d], 1);
    csr[pos] = s;
}

// ---------------------------------------------------------------------------
// One warp per node: out[i] = feat[i] + sum_{j in CSR(i)} feat[j].
template <int C>
__global__ void gather_kernel(const float* __restrict__ feat,
                              const int* __restrict__ offs,
                              const int* __restrict__ csr,
                              float* __restrict__ out, int N) {
    int node = (int)((blockIdx.x * blockDim.x + threadIdx.x) >> 5);
    int lane = threadIdx.x & 31;
    if (node >= N) return;
    int s = offs[node];
    int e = offs[node + 1];
    if (C == 64) {
        const float2* f2 = (const float2*)feat;
        float2 acc = f2[(long long)node * 32 + lane];
        int k = s;
        for (; k + 1 < e; k += 2) {
            int j0 = __ldg(&csr[k]);
            int j1 = __ldg(&csr[k + 1]);
            float2 v0 = f2[(long long)j0 * 32 + lane];
            float2 v1 = f2[(long long)j1 * 32 + lane];
            acc.x += v0.x + v1.x;
            acc.y += v0.y + v1.y;
        }
        if (k < e) {
            int j = __ldg(&csr[k]);
            float2 v = f2[(long long)j * 32 + lane];
            acc.x += v.x;
            acc.y += v.y;
        }
        ((float2*)out)[(long long)node * 32 + lane] = acc;
    } else {
        const float4* f4 = (const float4*)feat;
        float4 acc = f4[(long long)node * 32 + lane];
        int k = s;
        for (; k + 1 < e; k += 2) {
            int j0 = __ldg(&csr[k]);
            int j1 = __ldg(&csr[k + 1]);
            float4 v0 = f4[(long long)j0 * 32 + lane];
            float4 v1 = f4[(long long)j1 * 32 + lane];
            acc.x += v0.x + v1.x;
            acc.y += v0.y + v1.y;
            acc.z += v0.z + v1.z;
            acc.w += v0.w + v1.w;
        }
        if (k < e) {
            int j = __ldg(&csr[k]);
            float4 v = f4[(long long)j * 32 + lane];
            acc.x += v.x; acc.y += v.y; acc.z += v.z; acc.w += v.w;
        }
        ((float4*)out)[(long long)node * 32 + lane] = acc;
    }
}

// ---------------------------------------------------------------------------
// Fused GEMM + bias (+ optional ReLU):  C[N,CO] = act(A[N,CI] @ W[CI,CO] + b)
// BM=64 rows/block, BK=32, 256 threads (16 row-groups x 16 col-groups),
// TM=4 x TN=CO/16 microtiles. ~60 regs -> 4 CTAs/SM.
template <int CI, int CO, int RELU>
__launch_bounds__(256, 4)
__global__ void gemm_bias_kernel(const float* __restrict__ A,
                                 const float* __restrict__ W,
                                 const float* __restrict__ bias,
                                 float* __restrict__ Cmat, int Nrows) {
    constexpr int BM = 64;
    constexpr int BK = 32;
    constexpr int BN = CO;          // 64 or 128
    constexpr int TM = 4;
    constexpr int TN = BN / 16;     // 8 (CO=128) or 4 (CO=64)

    __shared__ float As[BK][BM + 1];   // +1 pad: conflict-free transposed stores
    __shared__ float Bs[BK][BN];

    const int tid = threadIdx.x;                 // 0..255
    const int tr  = tid >> 4;                    // 0..15 (row group)
    const int tc  = tid & 15;                    // 0..15 (col group)
    const long long rowBase = (long long)blockIdx.x * BM;

    float acc[TM][TN];
#pragma unroll
    for (int i = 0; i < TM; ++i)
#pragma unroll
        for (int j = 0; j < TN; ++j) acc[i][j] = 0.f;

    for (int k0 = 0; k0 < CI; k0 += BK) {
        // --- A tile (BM x BK) transposed into smem; 2 float4 per thread ---
#pragma unroll
        for (int it = 0; it < (BM * BK) / (256 * 4); ++it) {
            int idx = tid + it * 256;
            int m   = idx >> 3;                // 8 float4 per row (BK/4)
            int kq  = idx & 7;
            long long row = rowBase + m;
            float4 v = make_float4(0.f, 0.f, 0.f, 0.f);
            if (row < Nrows)
                v = ((const float4*)(A + row * CI + k0))[kq];
            As[kq * 4 + 0][m] = v.x;
            As[kq * 4 + 1][m] = v.y;
            As[kq * 4 + 2][m] = v.z;
            As[kq * 4 + 3][m] = v.w;
        }
        // --- W tile (BK x BN) ---
#pragma unroll
        for (int it = 0; it < (BK * BN) / (256 * 4); ++it) {
            int idx = tid + it * 256;
            int k   = idx / (BN / 4);
            int nq  = idx % (BN / 4);
            float4 v = ((const float4*)(W + (long long)(k0 + k) * CO))[nq];
            *((float4*)&Bs[k][nq * 4]) = v;
        }
        __syncthreads();

#pragma unroll
        for (int k = 0; k < BK; ++k) {
            float a[TM], b[TN];
#pragma unroll
            for (int i = 0; i < TM; ++i) a[i] = As[k][tr * TM + i];
#pragma unroll
            for (int j = 0; j < TN; ++j) b[j] = Bs[k][tc * TN + j];
#pragma unroll
            for (int i = 0; i < TM; ++i)
#pragma unroll
                for (int j = 0; j < TN; ++j) acc[i][j] += a[i] * b[j];
        }
        __syncthreads();
    }

#pragma unroll
    for (int i = 0; i < TM; ++i) {
        long long row = rowBase + tr * TM + i;
        if (row >= Nrows) continue;
#pragma unroll
        for (int j = 0; j < TN; ++j) {
            int n = tc * TN + j;
            float c = acc[i][j] + bias[n];
            if (RELU) c = fmaxf(c, 0.f);
            Cmat[row * CO + n] = c;
        }
    }
}

// ---------------------------------------------------------------------------
extern "C" void kernel_launch(void* const* d_in, const int* in_sizes, int n_in,
                              void* d_out, int out_size) {
    const float* x  = (const float*)d_in[0];
    const void*  ei = d_in[1];
    const float* W1 = (const float*)d_in[2];
    const float* b1 = (const float*)d_in[3];
    const float* W2 = (const float*)d_in[4];
    const float* b2 = (const float*)d_in[5];
    const float* W3 = (const float*)d_in[6];
    const float* b3 = (const float*)d_in[7];
    const float* W4 = (const float*)d_in[8];
    const float* b4 = (const float*)d_in[9];

    const int N = in_sizes[0] / CIN;
    const int E = in_sizes[1] / 2;

    float *h1pre, *t1, *h, *h2pre, *t2;
    cudaGetSymbolAddress((void**)&h1pre, g_h1pre);
    cudaGetSymbolAddress((void**)&t1,    g_t1);
    cudaGetSymbolAddress((void**)&h,     g_h);
    cudaGetSymbolAddress((void**)&h2pre, g_h2pre);
    cudaGetSymbolAddress((void**)&t2,    g_t2);
    int *deg, *offs, *cursor, *csr;
    cudaGetSymbolAddress((void**)&deg,    g_deg);
    cudaGetSymbolAddress((void**)&offs,   g_offs);
    cudaGetSymbolAddress((void**)&cursor, g_cursor);
    cudaGetSymbolAddress((void**)&csr,    g_csr);

    float* out = (float*)d_out;
    const int gemm_blocks   = (N + 63) / 64;
    const int edge_blocks   = (E + 255) / 256;
    const int gather_blocks = (N * 32 + 255) / 256;   // 1 warp per node, 8 warps/block

    // ---- CSR build (shared by both layers) ----
    detect_idx_kernel<<<1, 32>>>((const unsigned*)ei);
    zero_kernel<<<(N + 255) / 256, 256>>>(deg, N);
    hist_kernel<<<edge_blocks, 256>>>(ei, deg, E);
    scan_kernel<<<1, 1024>>>(deg, offs, cursor, N);
    fill_kernel<<<edge_blocks, 256>>>(ei, cursor, csr, E);

    // ---- Layer 1 ----
    gather_kernel<CIN><<<gather_blocks, 256>>>(x, offs, csr, h1pre, N);
    gemm_bias_kernel<CIN,  CHID, 1><<<gemm_blocks, 256>>>(h1pre, W1, b1, t1, N);
    gemm_bias_kernel<CHID, CHID, 1><<<gemm_blocks, 256>>>(t1,    W2, b2, h,  N);

    // ---- Layer 2 ----
    gather_kernel<CHID><<<gather_blocks, 256>>>(h, offs, csr, h2pre, N);
    gemm_bias_kernel<CHID, CHID, 1><<<gemm_blocks, 256>>>(h2pre, W3, b3, t2,  N);
    gemm_bias_kernel<CHID, CIN,  0><<<gemm_blocks, 256>>>(t2,    W4, b4, out, N);
}

// round 4
// speedup vs baseline: 1.4976x; 1.0535x over previous
#include <cuda_runtime.h>

// ---------------------------------------------------------------------------
// GIN (2 layers) on GB300 — CSR-gather aggregation + register-tiled SGEMMs.
//   CSR build (once per launch): histogram -> hierarchical scan -> fill
//   h1pre = x + gather_sum(x, CSR)                    [N,64]
//   t1    = relu(h1pre @ W1 + b1)                     [N,128]
//   h     = relu(t1    @ W2 + b2)                     [N,128]
//   h2pre = h + gather_sum(h, CSR)                    [N,128]
//   t2    = relu(h2pre @ W3 + b3)                     [N,128]
//   out   = t2 @ W4 + b4                              [N,64]
// edge_index dtype (int32 vs int64) detected on-device (g_is64).
// ---------------------------------------------------------------------------

#define NMAX 50000
#define EMAX 800000
#define CIN  64
#define CHID 128
#define SCAN_BS 1024
#define MAXPART 256

__device__ float g_h1pre[NMAX * CIN];
__device__ float g_t1   [NMAX * CHID];
__device__ float g_h    [NMAX * CHID];
__device__ float g_h2pre[NMAX * CHID];
__device__ float g_t2   [NMAX * CHID];

__device__ int g_deg   [NMAX];
__device__ int g_offs  [NMAX + 1];
__device__ int g_cursor[NMAX];
__device__ int g_csr   [EMAX];
__device__ int g_part  [MAXPART];
__device__ unsigned g_is64;

// ---------------------------------------------------------------------------
__global__ void detect_idx_kernel(const unsigned* __restrict__ ei_u32) {
    if (threadIdx.x == 0 && blockIdx.x == 0) {
        unsigned acc = 0;
#pragma unroll 8
        for (int i = 0; i < 512; ++i) acc |= ei_u32[2 * i + 1];
        g_is64 = (acc == 0u) ? 1u : 0u;
    }
}

__global__ void zero_kernel(int* __restrict__ p, int n) {
    int i = blockIdx.x * blockDim.x + threadIdx.x;
    if (i < n) p[i] = 0;
}

__global__ void hist_kernel(const void* __restrict__ ei, int* __restrict__ deg, int E) {
    int e = blockIdx.x * blockDim.x + threadIdx.x;
    if (e >= E) return;
    int d = g_is64 ? (int)((const long long*)ei)[E + e] : ((const int*)ei)[E + e];
    atomicAdd(&deg[d], 1);
}

// Phase 1: per-block exclusive scan of 1024 elems; write local scan + block sum.
__global__ void scan1_kernel(const int* __restrict__ deg, int* __restrict__ offs,
                             int* __restrict__ part, int N) {
    __shared__ int wsum[32];
    const int tid = threadIdx.x, lane = tid & 31, wid = tid >> 5;
    int i = blockIdx.x * SCAN_BS + tid;
    int v = (i < N) ? deg[i] : 0;
    int x = v;
#pragma unroll
    for (int o = 1; o < 32; o <<= 1) {
        int y = __shfl_up_sync(0xffffffffu, x, o);
        if (lane >= o) x += y;
    }
    if (lane == 31) wsum[wid] = x;
    __syncthreads();
    if (wid == 0) {
        int w = wsum[lane];
#pragma unroll
        for (int o = 1; o < 32; o <<= 1) {
            int y = __shfl_up_sync(0xffffffffu, w, o);
            if (lane >= o) w += y;
        }
        wsum[lane] = w;
    }
    __syncthreads();
    int warpoff = (wid > 0) ? wsum[wid - 1] : 0;
    if (i < N) offs[i] = warpoff + x - v;      // block-local exclusive
    if (tid == SCAN_BS - 1) part[blockIdx.x] = warpoff + x;  // block total
}

// Phase 2: exclusive scan of block partials (single small block); writes total.
__global__ void scan2_kernel(int* __restrict__ part, int* __restrict__ offs,
                             int nblk, int N) {
    __shared__ int s[MAXPART];
    int tid = threadIdx.x;
    int v = (tid < nblk) ? part[tid] : 0;
    s[tid] = v;
    __syncthreads();
    // Hillis-Steele inclusive scan over MAXPART
    for (int o = 1; o < MAXPART; o <<= 1) {
        int y = (tid >= o) ? s[tid - o] : 0;
        __syncthreads();
        s[tid] += y;
        __syncthreads();
    }
    if (tid < nblk) part[tid] = s[tid] - v;    // exclusive
    if (tid == MAXPART - 1) offs[N] = s[tid];  // grand total
}

// Phase 3: add block offsets; mirror into cursor.
__global__ void scan3_kernel(int* __restrict__ offs, int* __restrict__ cursor,
                             const int* __restrict__ part, int N) {
    int i = blockIdx.x * SCAN_BS + threadIdx.x;
    if (i < N) {
        int v = offs[i] + part[blockIdx.x];
        offs[i] = v;
        cursor[i] = v;
    }
}

__global__ void fill_kernel(const void* __restrict__ ei, int* __restrict__ cursor,
                            int* __restrict__ csr, int E) {
    int e = blockIdx.x * blockDim.x + threadIdx.x;
    if (e >= E) return;
    int s, d;
    if (g_is64) {
        const long long* p = (const long long*)ei;
        s = (int)p[e];
        d = (int)p[E + e];
    } else {
        const int* p = (const int*)ei;
        s = p[e];
        d = p[E + e];
    }
    int pos = atomicAdd(&cursor[d], 1);
    csr[pos] = s;
}

// ---------------------------------------------------------------------------
// C=64: two nodes per warp, 16 lanes x float4 per node row (256B coalesced).
__global__ void gather64_kernel(const float* __restrict__ feat,
                                const int* __restrict__ offs,
                                const int* __restrict__ csr,
                                float* __restrict__ out, int N) {
    int t = blockIdx.x * blockDim.x + threadIdx.x;
    int node = t >> 4;
    int lane = threadIdx.x & 15;
    if (node >= N) return;
    int s = offs[node];
    int e = offs[node + 1];
    const float4* f4 = (const float4*)feat;
    float4 acc = f4[(long long)node * 16 + lane];
    int k = s;
    for (; k + 1 < e; k += 2) {
        int j0 = __ldg(&csr[k]);
        int j1 = __ldg(&csr[k + 1]);
        float4 v0 = f4[(long long)j0 * 16 + lane];
        float4 v1 = f4[(long long)j1 * 16 + lane];
        acc.x += v0.x + v1.x;
        acc.y += v0.y + v1.y;
        acc.z += v0.z + v1.z;
        acc.w += v0.w + v1.w;
    }
    if (k < e) {
        int j = __ldg(&csr[k]);
        float4 v = f4[(long long)j * 16 + lane];
        acc.x += v.x; acc.y += v.y; acc.z += v.z; acc.w += v.w;
    }
    ((float4*)out)[(long long)node * 16 + lane] = acc;
}

// C=128: one warp per node, 32 lanes x float4 (512B per row).
__global__ void gather128_kernel(const float* __restrict__ feat,
                                 const int* __restrict__ offs,
                                 const int* __restrict__ csr,
                                 float* __restrict__ out, int N) {
    int node = (int)((blockIdx.x * blockDim.x + threadIdx.x) >> 5);
    int lane = threadIdx.x & 31;
    if (node >= N) return;
    int s = offs[node];
    int e = offs[node + 1];
    const float4* f4 = (const float4*)feat;
    float4 acc = f4[(long long)node * 32 + lane];
    int k = s;
    for (; k + 1 < e; k += 2) {
        int j0 = __ldg(&csr[k]);
        int j1 = __ldg(&csr[k + 1]);
        float4 v0 = f4[(long long)j0 * 32 + lane];
        float4 v1 = f4[(long long)j1 * 32 + lane];
        acc.x += v0.x + v1.x;
        acc.y += v0.y + v1.y;
        acc.z += v0.z + v1.z;
        acc.w += v0.w + v1.w;
    }
    if (k < e) {
        int j = __ldg(&csr[k]);
        float4 v = f4[(long long)j * 32 + lane];
        acc.x += v.x; acc.y += v.y; acc.z += v.z; acc.w += v.w;
    }
    ((float4*)out)[(long long)node * 32 + lane] = acc;
}

// ---------------------------------------------------------------------------
// Fused GEMM + bias (+ optional ReLU):  C[N,CO] = act(A[N,CI] @ W[CI,CO] + b)
// BM=64 rows/block, BK=32, 256 threads, TM=4 x TN=CO/16 microtiles.
template <int CI, int CO, int RELU>
__launch_bounds__(256, 4)
__global__ void gemm_bias_kernel(const float* __restrict__ A,
                                 const float* __restrict__ W,
                                 const float* __restrict__ bias,
                                 float* __restrict__ Cmat, int Nrows) {
    constexpr int BM = 64;
    constexpr int BK = 32;
    constexpr int BN = CO;
    constexpr int TM = 4;
    constexpr int TN = BN / 16;

    __shared__ float As[BK][BM + 1];
    __shared__ float Bs[BK][BN];

    const int tid = threadIdx.x;
    const int tr  = tid >> 4;
    const int tc  = tid & 15;
    const long long rowBase = (long long)blockIdx.x * BM;

    float acc[TM][TN];
#pragma unroll
    for (int i = 0; i < TM; ++i)
#pragma unroll
        for (int j = 0; j < TN; ++j) acc[i][j] = 0.f;

    for (int k0 = 0; k0 < CI; k0 += BK) {
#pragma unroll
        for (int it = 0; it < (BM * BK) / (256 * 4); ++it) {
            int idx = tid + it * 256;
            int m   = idx >> 3;
            int kq  = idx & 7;
            long long row = rowBase + m;
            float4 v = make_float4(0.f, 0.f, 0.f, 0.f);
            if (row < Nrows)
                v = ((const float4*)(A + row * CI + k0))[kq];
            As[kq * 4 + 0][m] = v.x;
            As[kq * 4 + 1][m] = v.y;
            As[kq * 4 + 2][m] = v.z;
            As[kq * 4 + 3][m] = v.w;
        }
#pragma unroll
        for (int it = 0; it < (BK * BN) / (256 * 4); ++it) {
            int idx = tid + it * 256;
            int k   = idx / (BN / 4);
            int nq  = idx % (BN / 4);
            float4 v = ((const float4*)(W + (long long)(k0 + k) * CO))[nq];
            *((float4*)&Bs[k][nq * 4]) = v;
        }
        __syncthreads();

#pragma unroll
        for (int k = 0; k < BK; ++k) {
            float a[TM], b[TN];
#pragma unroll
            for (int i = 0; i < TM; ++i) a[i] = As[k][tr * TM + i];
#pragma unroll
            for (int j = 0; j < TN; ++j) b[j] = Bs[k][tc * TN + j];
#pragma unroll
            for (int i = 0; i < TM; ++i)
#pragma unroll
                for (int j = 0; j < TN; ++j) acc[i][j] += a[i] * b[j];
        }
        __syncthreads();
    }

#pragma unroll
    for (int i = 0; i < TM; ++i) {
        long long row = rowBase + tr * TM + i;
        if (row >= Nrows) continue;
#pragma unroll
        for (int j = 0; j < TN; ++j) {
            int n = tc * TN + j;
            float c = acc[i][j] + bias[n];
            if (RELU) c = fmaxf(c, 0.f);
            Cmat[row * CO + n] = c;
        }
    }
}

// ---------------------------------------------------------------------------
extern "C" void kernel_launch(void* const* d_in, const int* in_sizes, int n_in,
                              void* d_out, int out_size) {
    const float* x  = (const float*)d_in[0];
    const void*  ei = d_in[1];
    const float* W1 = (const float*)d_in[2];
    const float* b1 = (const float*)d_in[3];
    const float* W2 = (const float*)d_in[4];
    const float* b2 = (const float*)d_in[5];
    const float* W3 = (const float*)d_in[6];
    const float* b3 = (const float*)d_in[7];
    const float* W4 = (const float*)d_in[8];
    const float* b4 = (const float*)d_in[9];

    const int N = in_sizes[0] / CIN;
    const int E = in_sizes[1] / 2;

    float *h1pre, *t1, *h, *h2pre, *t2;
    cudaGetSymbolAddress((void**)&h1pre, g_h1pre);
    cudaGetSymbolAddress((void**)&t1,    g_t1);
    cudaGetSymbolAddress((void**)&h,     g_h);
    cudaGetSymbolAddress((void**)&h2pre, g_h2pre);
    cudaGetSymbolAddress((void**)&t2,    g_t2);
    int *deg, *offs, *cursor, *csr, *part;
    cudaGetSymbolAddress((void**)&deg,    g_deg);
    cudaGetSymbolAddress((void**)&offs,   g_offs);
    cudaGetSymbolAddress((void**)&cursor, g_cursor);
    cudaGetSymbolAddress((void**)&csr,    g_csr);
    cudaGetSymbolAddress((void**)&part,   g_part);

    float* out = (float*)d_out;
    const int gemm_blocks = (N + 63) / 64;
    const int edge_blocks = (E + 255) / 256;
    const int scan_blocks = (N + SCAN_BS - 1) / SCAN_BS;   // 49
    const int g64_blocks  = (N * 16 + 255) / 256;
    const int g128_blocks = (N * 32 + 255) / 256;

    // ---- CSR build (shared by both layers) ----
    detect_idx_kernel<<<1, 32>>>((const unsigned*)ei);
    zero_kernel<<<(N + 255) / 256, 256>>>(deg, N);
    hist_kernel<<<edge_blocks, 256>>>(ei, deg, E);
    scan1_kernel<<<scan_blocks, SCAN_BS>>>(deg, offs, part, N);
    scan2_kernel<<<1, MAXPART>>>(part, offs, scan_blocks, N);
    scan3_kernel<<<scan_blocks, SCAN_BS>>>(offs, cursor, part, N);
    fill_kernel<<<edge_blocks, 256>>>(ei, cursor, csr, E);

    // ---- Layer 1 ----
    gather64_kernel<<<g64_blocks, 256>>>(x, offs, csr, h1pre, N);
    gemm_bias_kernel<CIN,  CHID, 1><<<gemm_blocks, 256>>>(h1pre, W1, b1, t1, N);
    gemm_bias_kernel<CHID, CHID, 1><<<gemm_blocks, 256>>>(t1,    W2, b2, h,  N);

    // ---- Layer 2 ----
    gather128_kernel<<<g128_blocks, 256>>>(h, offs, csr, h2pre, N);
    gemm_bias_kernel<CHID, CHID, 1><<<gemm_blocks, 256>>>(h2pre, W3, b3, t2,  N);
    gemm_bias_kernel<CHID, CIN,  0><<<gemm_blocks, 256>>>(t2,    W4, b4, out, N);
}

// round 6
// speedup vs baseline: 1.6549x; 1.1051x over previous
#include <cuda_runtime.h>
#include <cstdint>

// ---------------------------------------------------------------------------
// GIN (2 layers) on GB300 — CSR-gather aggregation + f32x2-packed SGEMMs.
// tcgen05 is unavailable (harness PTX target is compute_103, not 103a), so
// the GEMMs use HW FFMA2 via PTX fma.rn.f32x2 (2 fp32 FMA per issue slot).
// ---------------------------------------------------------------------------

#define NMAX 50000
#define EMAX 800000
#define CIN  64
#define CHID 128
#define SCAN_BS 1024
#define MAXPART 256

__device__ float g_h1pre[NMAX * CIN];
__device__ float g_t1   [NMAX * CHID];
__device__ float g_h    [NMAX * CHID];
__device__ float g_h2pre[NMAX * CHID];
__device__ float g_t2   [NMAX * CHID];

__device__ int g_deg   [NMAX];
__device__ int g_offs  [NMAX + 1];
__device__ int g_cursor[NMAX];
__device__ int g_csr   [EMAX];
__device__ int g_part  [MAXPART];
__device__ unsigned g_is64;

// ======================= CSR build =========================================
__global__ void detect_idx_kernel(const unsigned* __restrict__ ei_u32) {
    if (threadIdx.x == 0 && blockIdx.x == 0) {
        unsigned acc = 0;
#pragma unroll 8
        for (int i = 0; i < 512; ++i) acc |= ei_u32[2 * i + 1];
        g_is64 = (acc == 0u) ? 1u : 0u;
    }
}
__global__ void zero_kernel(int* __restrict__ p, int n) {
    int i = blockIdx.x * blockDim.x + threadIdx.x;
    if (i < n) p[i] = 0;
}
__global__ void hist_kernel(const void* __restrict__ ei, int* __restrict__ deg, int E) {
    int e = blockIdx.x * blockDim.x + threadIdx.x;
    if (e >= E) return;
    int d = g_is64 ? (int)((const long long*)ei)[E + e] : ((const int*)ei)[E + e];
    atomicAdd(&deg[d], 1);
}
__global__ void scan1_kernel(const int* __restrict__ deg, int* __restrict__ offs,
                             int* __restrict__ part, int N) {
    __shared__ int wsum[32];
    const int tid = threadIdx.x, lane = tid & 31, wid = tid >> 5;
    int i = blockIdx.x * SCAN_BS + tid;
    int v = (i < N) ? deg[i] : 0;
    int x = v;
#pragma unroll
    for (int o = 1; o < 32; o <<= 1) {
        int y = __shfl_up_sync(0xffffffffu, x, o);
        if (lane >= o) x += y;
    }
    if (lane == 31) wsum[wid] = x;
    __syncthreads();
    if (wid == 0) {
        int w = wsum[lane];
#pragma unroll
        for (int o = 1; o < 32; o <<= 1) {
            int y = __shfl_up_sync(0xffffffffu, w, o);
            if (lane >= o) w += y;
        }
        wsum[lane] = w;
    }
    __syncthreads();
    int warpoff = (wid > 0) ? wsum[wid - 1] : 0;
    if (i < N) offs[i] = warpoff + x - v;
    if (tid == SCAN_BS - 1) part[blockIdx.x] = warpoff + x;
}
__global__ void scan2_kernel(int* __restrict__ part, int* __restrict__ offs,
                             int nblk, int N) {
    __shared__ int s[MAXPART];
    int tid = threadIdx.x;
    int v = (tid < nblk) ? part[tid] : 0;
    s[tid] = v;
    __syncthreads();
    for (int o = 1; o < MAXPART; o <<= 1) {
        int y = (tid >= o) ? s[tid - o] : 0;
        __syncthreads();
        s[tid] += y;
        __syncthreads();
    }
    if (tid < nblk) part[tid] = s[tid] - v;
    if (tid == MAXPART - 1) offs[N] = s[tid];
}
__global__ void scan3_kernel(int* __restrict__ offs, int* __restrict__ cursor,
                             const int* __restrict__ part, int N) {
    int i = blockIdx.x * SCAN_BS + threadIdx.x;
    if (i < N) {
        int v = offs[i] + part[blockIdx.x];
        offs[i] = v;
        cursor[i] = v;
    }
}
__global__ void fill_kernel(const void* __restrict__ ei, int* __restrict__ cursor,
                            int* __restrict__ csr, int E) {
    int e = blockIdx.x * blockDim.x + threadIdx.x;
    if (e >= E) return;
    int s, d;
    if (g_is64) {
        const long long* p = (const long long*)ei;
        s = (int)p[e];
        d = (int)p[E + e];
    } else {
        const int* p = (const int*)ei;
        s = p[e];
        d = p[E + e];
    }
    int pos = atomicAdd(&cursor[d], 1);
    csr[pos] = s;
}

// ======================= gathers ===========================================
__global__ void gather64_kernel(const float* __restrict__ feat,
                                const int* __restrict__ offs,
                                const int* __restrict__ csr,
                                float* __restrict__ out, int N) {
    int t = blockIdx.x * blockDim.x + threadIdx.x;
    int node = t >> 4;
    int lane = threadIdx.x & 15;
    if (node >= N) return;
    int s = offs[node], e = offs[node + 1];
    const float4* f4 = (const float4*)feat;
    float4 acc = f4[(long long)node * 16 + lane];
    int k = s;
    for (; k + 1 < e; k += 2) {
        int j0 = __ldg(&csr[k]);
        int j1 = __ldg(&csr[k + 1]);
        float4 v0 = f4[(long long)j0 * 16 + lane];
        float4 v1 = f4[(long long)j1 * 16 + lane];
        acc.x += v0.x + v1.x; acc.y += v0.y + v1.y;
        acc.z += v0.z + v1.z; acc.w += v0.w + v1.w;
    }
    if (k < e) {
        int j = __ldg(&csr[k]);
        float4 v = f4[(long long)j * 16 + lane];
        acc.x += v.x; acc.y += v.y; acc.z += v.z; acc.w += v.w;
    }
    ((float4*)out)[(long long)node * 16 + lane] = acc;
}
__global__ void gather128_kernel(const float* __restrict__ feat,
                                 const int* __restrict__ offs,
                                 const int* __restrict__ csr,
                                 float* __restrict__ out, int N) {
    int node = (int)((blockIdx.x * blockDim.x + threadIdx.x) >> 5);
    int lane = threadIdx.x & 31;
    if (node >= N) return;
    int s = offs[node], e = offs[node + 1];
    const float4* f4 = (const float4*)feat;
    float4 acc = f4[(long long)node * 32 + lane];
    int k = s;
    for (; k + 1 < e; k += 2) {
        int j0 = __ldg(&csr[k]);
        int j1 = __ldg(&csr[k + 1]);
        float4 v0 = f4[(long long)j0 * 32 + lane];
        float4 v1 = f4[(long long)j1 * 32 + lane];
        acc.x += v0.x + v1.x; acc.y += v0.y + v1.y;
        acc.z += v0.z + v1.z; acc.w += v0.w + v1.w;
    }
    if (k < e) {
        int j = __ldg(&csr[k]);
        float4 v = f4[(long long)j * 32 + lane];
        acc.x += v.x; acc.y += v.y; acc.z += v.z; acc.w += v.w;
    }
    ((float4*)out)[(long long)node * 32 + lane] = acc;
}

// ======================= f32x2 packed GEMM =================================
// C[N,CO] = act(A[N,CI] @ W[CI,CO] + b)
// BM=64 rows/block, BK=32, 256 threads, TM=4 x TN=CO/16 microtiles,
// accumulators packed 2-wide along N -> fma.rn.f32x2 (FFMA2).
#define FMA2(acc_, a_, b_) \
    asm("fma.rn.f32x2 %0, %1, %2, %0;" : "+l"(acc_) : "l"(a_), "l"(b_))
#define PACK2(dst_, v_) \
    asm("mov.b64 %0, {%1, %1};" : "=l"(dst_) : "r"(__float_as_uint(v_)))

template <int CI, int CO, int RELU>
__launch_bounds__(256, 4)
__global__ void gemm_bias_kernel(const float* __restrict__ A,
                                 const float* __restrict__ W,
                                 const float* __restrict__ bias,
                                 float* __restrict__ Cmat, int Nrows) {
    constexpr int BM = 64;
    constexpr int BK = 32;
    constexpr int BN = CO;          // 64 or 128
    constexpr int TM = 4;
    constexpr int TN = BN / 16;     // 8 (CO=128) or 4 (CO=64)
    constexpr int TP = TN / 2;      // packed pairs: 4 or 2

    __shared__ float As[BK][BM + 4];   // +4 pad: rows stay 16B-aligned
    __shared__ float Bs[BK][BN];

    const int tid = threadIdx.x;
    const int tr  = tid >> 4;          // 0..15 row group
    const int tc  = tid & 15;          // 0..15 col group
    const long long rowBase = (long long)blockIdx.x * BM;

    unsigned long long acc[TM][TP];
#pragma unroll
    for (int i = 0; i < TM; ++i)
#pragma unroll
        for (int j = 0; j < TP; ++j) acc[i][j] = 0ull;

    for (int k0 = 0; k0 < CI; k0 += BK) {
        // --- A tile (BM x BK) transposed into smem ---
#pragma unroll
        for (int it = 0; it < (BM * BK) / (256 * 4); ++it) {
            int idx = tid + it * 256;
            int m   = idx >> 3;
            int kq  = idx & 7;
            long long row = rowBase + m;
            float4 v = make_float4(0.f, 0.f, 0.f, 0.f);
            if (row < Nrows)
                v = ((const float4*)(A + row * CI + k0))[kq];
            As[kq * 4 + 0][m] = v.x;
            As[kq * 4 + 1][m] = v.y;
            As[kq * 4 + 2][m] = v.z;
            As[kq * 4 + 3][m] = v.w;
        }
        // --- W tile (BK x BN) ---
#pragma unroll
        for (int it = 0; it < (BK * BN) / (256 * 4); ++it) {
            int idx = tid + it * 256;
            int k   = idx / (BN / 4);
            int nq  = idx % (BN / 4);
            float4 v = ((const float4*)(W + (long long)(k0 + k) * CO))[nq];
            *((float4*)&Bs[k][nq * 4]) = v;
        }
        __syncthreads();

#pragma unroll
        for (int k = 0; k < BK; ++k) {
            float4 av = *(const float4*)&As[k][tr * TM];
            unsigned long long bp[TP];
            *(ulonglong2*)&bp[0] = *(const ulonglong2*)&Bs[k][tc * TN];
            if (TP == 4)
                *(ulonglong2*)&bp[2] = *(const ulonglong2*)&Bs[k][tc * TN + 4];
            unsigned long long ap[TM];
            PACK2(ap[0], av.x);
            PACK2(ap[1], av.y);
            PACK2(ap[2], av.z);
            PACK2(ap[3], av.w);
#pragma unroll
            for (int i = 0; i < TM; ++i)
#pragma unroll
                for (int j = 0; j < TP; ++j)
                    FMA2(acc[i][j], ap[i], bp[j]);
        }
        __syncthreads();
    }

    // --- epilogue: unpack, bias (+relu), store ---
#pragma unroll
    for (int i = 0; i < TM; ++i) {
        long long row = rowBase + tr * TM + i;
        if (row >= Nrows) continue;
#pragma unroll
        for (int j = 0; j < TP; ++j) {
            uint32_t lo, hi;
            asm("mov.b64 {%0, %1}, %2;" : "=r"(lo), "=r"(hi) : "l"(acc[i][j]));
            int n = tc * TN + j * 2;
            float c0 = __uint_as_float(lo) + bias[n];
            float c1 = __uint_as_float(hi) + bias[n + 1];
            if (RELU) { c0 = fmaxf(c0, 0.f); c1 = fmaxf(c1, 0.f); }
            float2 o = make_float2(c0, c1);
            *(float2*)(Cmat + row * CO + n) = o;
        }
    }
}

// ---------------------------------------------------------------------------
extern "C" void kernel_launch(void* const* d_in, const int* in_sizes, int n_in,
                              void* d_out, int out_size) {
    const float* x  = (const float*)d_in[0];
    const void*  ei = d_in[1];
    const float* W1 = (const float*)d_in[2];
    const float* b1 = (const float*)d_in[3];
    const float* W2 = (const float*)d_in[4];
    const float* b2 = (const float*)d_in[5];
    const float* W3 = (const float*)d_in[6];
    const float* b3 = (const float*)d_in[7];
    const float* W4 = (const float*)d_in[8];
    const float* b4 = (const float*)d_in[9];

    const int N = in_sizes[0] / CIN;
    const int E = in_sizes[1] / 2;

    float *h1pre, *t1, *h, *h2pre, *t2;
    cudaGetSymbolAddress((void**)&h1pre, g_h1pre);
    cudaGetSymbolAddress((void**)&t1,    g_t1);
    cudaGetSymbolAddress((void**)&h,     g_h);
    cudaGetSymbolAddress((void**)&h2pre, g_h2pre);
    cudaGetSymbolAddress((void**)&t2,    g_t2);
    int *deg, *offs, *cursor, *csr, *part;
    cudaGetSymbolAddress((void**)&deg,    g_deg);
    cudaGetSymbolAddress((void**)&offs,   g_offs);
    cudaGetSymbolAddress((void**)&cursor, g_cursor);
    cudaGetSymbolAddress((void**)&csr,    g_csr);
    cudaGetSymbolAddress((void**)&part,   g_part);

    float* out = (float*)d_out;
    const int gemm_blocks = (N + 63) / 64;
    const int edge_blocks = (E + 255) / 256;
    const int scan_blocks = (N + SCAN_BS - 1) / SCAN_BS;
    const int g64_blocks  = (N * 16 + 255) / 256;
    const int g128_blocks = (N * 32 + 255) / 256;

    // ---- CSR build (shared by both layers) ----
    detect_idx_kernel<<<1, 32>>>((const unsigned*)ei);
    zero_kernel<<<(N + 255) / 256, 256>>>(deg, N);
    hist_kernel<<<edge_blocks, 256>>>(ei, deg, E);
    scan1_kernel<<<scan_blocks, SCAN_BS>>>(deg, offs, part, N);
    scan2_kernel<<<1, MAXPART>>>(part, offs, scan_blocks, N);
    scan3_kernel<<<scan_blocks, SCAN_BS>>>(offs, cursor, part, N);
    fill_kernel<<<edge_blocks, 256>>>(ei, cursor, csr, E);

    // ---- Layer 1 ----
    gather64_kernel<<<g64_blocks, 256>>>(x, offs, csr, h1pre, N);
    gemm_bias_kernel<CIN,  CHID, 1><<<gemm_blocks, 256>>>(h1pre, W1, b1, t1, N);
    gemm_bias_kernel<CHID, CHID, 1><<<gemm_blocks, 256>>>(t1,    W2, b2, h,  N);

    // ---- Layer 2 ----
    gather128_kernel<<<g128_blocks, 256>>>(h, offs, csr, h2pre, N);
    gemm_bias_kernel<CHID, CHID, 1><<<gemm_blocks, 256>>>(h2pre, W3, b3, t2,  N);
    gemm_bias_kernel<CHID, CIN,  0><<<gemm_blocks, 256>>>(t2,    W4, b4, out, N);
}

// round 7
// speedup vs baseline: 1.7133x; 1.0353x over previous
#include <cuda_runtime.h>
#include <cstdint>

// ---------------------------------------------------------------------------
// GIN (2 layers) on GB300 — CSR-gather aggregation + f32x2 SGEMMs.
// GEMM: 64x64 tiles, 128 thr/CTA, 8 CTA/SM, pre-splatted A smem (no packs),
// fma.rn.f32x2 (FFMA2) microkernel.
// ---------------------------------------------------------------------------

#define NMAX 50000
#define EMAX 800000
#define CIN  64
#define CHID 128
#define SCAN_BS 1024
#define MAXPART 256

__device__ float g_h1pre[NMAX * CIN];
__device__ float g_t1   [NMAX * CHID];
__device__ float g_h    [NMAX * CHID];
__device__ float g_h2pre[NMAX * CHID];
__device__ float g_t2   [NMAX * CHID];

__device__ int g_deg   [NMAX];
__device__ int g_offs  [NMAX + 1];
__device__ int g_cursor[NMAX];
__device__ int g_csr   [EMAX];
__device__ int g_part  [MAXPART];
__device__ unsigned g_is64;

// ======================= CSR build =========================================
__global__ void detect_idx_kernel(const unsigned* __restrict__ ei_u32) {
    if (threadIdx.x == 0 && blockIdx.x == 0) {
        unsigned acc = 0;
#pragma unroll 8
        for (int i = 0; i < 512; ++i) acc |= ei_u32[2 * i + 1];
        g_is64 = (acc == 0u) ? 1u : 0u;
    }
}
__global__ void zero_kernel(int* __restrict__ p, int n) {
    int i = blockIdx.x * blockDim.x + threadIdx.x;
    if (i < n) p[i] = 0;
}
__global__ void hist_kernel(const void* __restrict__ ei, int* __restrict__ deg, int E) {
    int e = blockIdx.x * blockDim.x + threadIdx.x;
    if (e >= E) return;
    int d = g_is64 ? (int)((const long long*)ei)[E + e] : ((const int*)ei)[E + e];
    atomicAdd(&deg[d], 1);
}
__global__ void scan1_kernel(const int* __restrict__ deg, int* __restrict__ offs,
                             int* __restrict__ part, int N) {
    __shared__ int wsum[32];
    const int tid = threadIdx.x, lane = tid & 31, wid = tid >> 5;
    int i = blockIdx.x * SCAN_BS + tid;
    int v = (i < N) ? deg[i] : 0;
    int x = v;
#pragma unroll
    for (int o = 1; o < 32; o <<= 1) {
        int y = __shfl_up_sync(0xffffffffu, x, o);
        if (lane >= o) x += y;
    }
    if (lane == 31) wsum[wid] = x;
    __syncthreads();
    if (wid == 0) {
        int w = wsum[lane];
#pragma unroll
        for (int o = 1; o < 32; o <<= 1) {
            int y = __shfl_up_sync(0xffffffffu, w, o);
            if (lane >= o) w += y;
        }
        wsum[lane] = w;
    }
    __syncthreads();
    int warpoff = (wid > 0) ? wsum[wid - 1] : 0;
    if (i < N) offs[i] = warpoff + x - v;
    if (tid == SCAN_BS - 1) part[blockIdx.x] = warpoff + x;
}
__global__ void scan2_kernel(int* __restrict__ part, int* __restrict__ offs,
                             int nblk, int N) {
    __shared__ int s[MAXPART];
    int tid = threadIdx.x;
    int v = (tid < nblk) ? part[tid] : 0;
    s[tid] = v;
    __syncthreads();
    for (int o = 1; o < MAXPART; o <<= 1) {
        int y = (tid >= o) ? s[tid - o] : 0;
        __syncthreads();
        s[tid] += y;
        __syncthreads();
    }
    if (tid < nblk) part[tid] = s[tid] - v;
    if (tid == MAXPART - 1) offs[N] = s[tid];
}
__global__ void scan3_kernel(int* __restrict__ offs, int* __restrict__ cursor,
                             const int* __restrict__ part, int N) {
    int i = blockIdx.x * SCAN_BS + threadIdx.x;
    if (i < N) {
        int v = offs[i] + part[blockIdx.x];
        offs[i] = v;
        cursor[i] = v;
    }
}
__global__ void fill_kernel(const void* __restrict__ ei, int* __restrict__ cursor,
                            int* __restrict__ csr, int E) {
    int e = blockIdx.x * blockDim.x + threadIdx.x;
    if (e >= E) return;
    int s, d;
    if (g_is64) {
        const long long* p = (const long long*)ei;
        s = (int)p[e];
        d = (int)p[E + e];
    } else {
        const int* p = (const int*)ei;
        s = p[e];
        d = p[E + e];
    }
    int pos = atomicAdd(&cursor[d], 1);
    csr[pos] = s;
}

// ======================= gathers ===========================================
__global__ void gather64_kernel(const float* __restrict__ feat,
                                const int* __restrict__ offs,
                                const int* __restrict__ csr,
                                float* __restrict__ out, int N) {
    int t = blockIdx.x * blockDim.x + threadIdx.x;
    int node = t >> 4;
    int lane = threadIdx.x & 15;
    if (node >= N) return;
    int s = offs[node], e = offs[node + 1];
    const float4* f4 = (const float4*)feat;
    float4 acc = f4[(long long)node * 16 + lane];
    int k = s;
    for (; k + 1 < e; k += 2) {
        int j0 = __ldg(&csr[k]);
        int j1 = __ldg(&csr[k + 1]);
        float4 v0 = f4[(long long)j0 * 16 + lane];
        float4 v1 = f4[(long long)j1 * 16 + lane];
        acc.x += v0.x + v1.x; acc.y += v0.y + v1.y;
        acc.z += v0.z + v1.z; acc.w += v0.w + v1.w;
    }
    if (k < e) {
        int j = __ldg(&csr[k]);
        float4 v = f4[(long long)j * 16 + lane];
        acc.x += v.x; acc.y += v.y; acc.z += v.z; acc.w += v.w;
    }
    ((float4*)out)[(long long)node * 16 + lane] = acc;
}
__global__ void gather128_kernel(const float* __restrict__ feat,
                                 const int* __restrict__ offs,
                                 const int* __restrict__ csr,
                                 float* __restrict__ out, int N) {
    int node = (int)((blockIdx.x * blockDim.x + threadIdx.x) >> 5);
    int lane = threadIdx.x & 31;
    if (node >= N) return;
    int s = offs[node], e = offs[node + 1];
    const float4* f4 = (const float4*)feat;
    float4 acc = f4[(long long)node * 32 + lane];
    int k = s;
    for (; k + 1 < e; k += 2) {
        int j0 = __ldg(&csr[k]);
        int j1 = __ldg(&csr[k + 1]);
        float4 v0 = f4[(long long)j0 * 32 + lane];
        float4 v1 = f4[(long long)j1 * 32 + lane];
        acc.x += v0.x + v1.x; acc.y += v0.y + v1.y;
        acc.z += v0.z + v1.z; acc.w += v0.w + v1.w;
    }
    if (k < e) {
        int j = __ldg(&csr[k]);
        float4 v = f4[(long long)j * 32 + lane];
        acc.x += v.x; acc.y += v.y; acc.z += v.z; acc.w += v.w;
    }
    ((float4*)out)[(long long)node * 32 + lane] = acc;
}

// ======================= f32x2 packed GEMM (64x64 tiles) ===================
// C[N,COTOT] = act(A[N,CI] @ W[CI,COTOT] + b), column-split into BN=64 blocks.
// 128 threads (16 row-groups x 16 col-groups), TM=8 x TN=4 per thread.
// A smem pre-splatted: As[k][2m]=As[k][2m+1]=A[m][k] -> packed (a,a) pairs
// load directly as u64, no mov-splat in the inner loop.
#define FMA2(acc_, a_, b_) \
    asm("fma.rn.f32x2 %0, %1, %2, %0;" : "+l"(acc_) : "l"(a_), "l"(b_))

template <int CI, int COTOT, int RELU>
__launch_bounds__(128, 8)
__global__ void gemm_bias_kernel(const float* __restrict__ A,
                                 const float* __restrict__ W,
                                 const float* __restrict__ bias,
                                 float* __restrict__ Cmat, int Nrows) {
    constexpr int BM = 64;
    constexpr int BK = 32;
    constexpr int TM = 8;

    __shared__ float As[BK][2 * BM + 8];   // splatted A, row stride 136
    __shared__ float Bs[BK][64];

    const int tid = threadIdx.x;            // 0..127
    const int tr  = tid >> 4;               // 0..7  (row group, 8 rows each)
    const int tc  = tid & 15;               // 0..15 (col group, 4 cols each)
    const long long rowBase = (long long)blockIdx.x * BM;
    const int colBase = blockIdx.y * 64;

    unsigned long long acc[TM][2];
#pragma unroll
    for (int i = 0; i < TM; ++i) { acc[i][0] = 0ull; acc[i][1] = 0ull; }

    for (int k0 = 0; k0 < CI; k0 += BK) {
        // --- A tile (BM x BK): load float4, store splatted-transposed ---
#pragma unroll
        for (int it = 0; it < 4; ++it) {
            int idx = tid + it * 128;        // 512 float4 total
            int m   = idx >> 3;              // 0..63
            int kq  = idx & 7;               // 0..7
            long long row = rowBase + m;
            float4 v = make_float4(0.f, 0.f, 0.f, 0.f);
            if (row < Nrows)
                v = ((const float4*)(A + row * CI + k0))[kq];
            *(float2*)&As[kq * 4 + 0][2 * m] = make_float2(v.x, v.x);
            *(float2*)&As[kq * 4 + 1][2 * m] = make_float2(v.y, v.y);
            *(float2*)&As[kq * 4 + 2][2 * m] = make_float2(v.z, v.z);
            *(float2*)&As[kq * 4 + 3][2 * m] = make_float2(v.w, v.w);
        }
        // --- W tile (BK x 64) ---
#pragma unroll
        for (int it = 0; it < 4; ++it) {
            int idx = tid + it * 128;        // 512 float4 total
            int k   = idx >> 4;              // 0..31
            int nq  = idx & 15;              // 0..15
            float4 v = *(const float4*)(W + (long long)(k0 + k) * COTOT + colBase + nq * 4);
            *(float4*)&Bs[k][nq * 4] = v;
        }
        __syncthreads();

#pragma unroll
        for (int k = 0; k < BK; ++k) {
            ulonglong2 a01 = *(const ulonglong2*)&As[k][tr * 16];
            ulonglong2 a23 = *(const ulonglong2*)&As[k][tr * 16 + 4];
            ulonglong2 a45 = *(const ulonglong2*)&As[k][tr * 16 + 8];
            ulonglong2 a67 = *(const ulonglong2*)&As[k][tr * 16 + 12];
            ulonglong2 b   = *(const ulonglong2*)&Bs[k][tc * 4];
            FMA2(acc[0][0], a01.x, b.x); FMA2(acc[0][1], a01.x, b.y);
            FMA2(acc[1][0], a01.y, b.x); FMA2(acc[1][1], a01.y, b.y);
            FMA2(acc[2][0], a23.x, b.x); FMA2(acc[2][1], a23.x, b.y);
            FMA2(acc[3][0], a23.y, b.x); FMA2(acc[3][1], a23.y, b.y);
            FMA2(acc[4][0], a45.x, b.x); FMA2(acc[4][1], a45.x, b.y);
            FMA2(acc[5][0], a45.y, b.x); FMA2(acc[5][1], a45.y, b.y);
            FMA2(acc[6][0], a67.x, b.x); FMA2(acc[6][1], a67.x, b.y);
            FMA2(acc[7][0], a67.y, b.x); FMA2(acc[7][1], a67.y, b.y);
        }
        __syncthreads();
    }

    // --- epilogue: unpack, bias (+relu), STG.128 per row ---
    const int ncol = colBase + tc * 4;
    float4 bv = *(const float4*)(bias + ncol);
#pragma unroll
    for (int i = 0; i < TM; ++i) {
        long long row = rowBase + tr * TM + i;
        if (row >= Nrows) continue;
        uint32_t l0, h0, l1, h1;
        asm("mov.b64 {%0, %1}, %2;" : "=r"(l0), "=r"(h0) : "l"(acc[i][0]));
        asm("mov.b64 {%0, %1}, %2;" : "=r"(l1), "=r"(h1) : "l"(acc[i][1]));
        float4 o;
        o.x = __uint_as_float(l0) + bv.x;
        o.y = __uint_as_float(h0) + bv.y;
        o.z = __uint_as_float(l1) + bv.z;
        o.w = __uint_as_float(h1) + bv.w;
        if (RELU) {
            o.x = fmaxf(o.x, 0.f); o.y = fmaxf(o.y, 0.f);
            o.z = fmaxf(o.z, 0.f); o.w = fmaxf(o.w, 0.f);
        }
        *(float4*)(Cmat + row * COTOT + ncol) = o;
    }
}

// ---------------------------------------------------------------------------
extern "C" void kernel_launch(void* const* d_in, const int* in_sizes, int n_in,
                              void* d_out, int out_size) {
    const float* x  = (const float*)d_in[0];
    const void*  ei = d_in[1];
    const float* W1 = (const float*)d_in[2];
    const float* b1 = (const float*)d_in[3];
    const float* W2 = (const float*)d_in[4];
    const float* b2 = (const float*)d_in[5];
    const float* W3 = (const float*)d_in[6];
    const float* b3 = (const float*)d_in[7];
    const float* W4 = (const float*)d_in[8];
    const float* b4 = (const float*)d_in[9];

    const int N = in_sizes[0] / CIN;
    const int E = in_sizes[1] / 2;

    float *h1pre, *t1, *h, *h2pre, *t2;
    cudaGetSymbolAddress((void**)&h1pre, g_h1pre);
    cudaGetSymbolAddress((void**)&t1,    g_t1);
    cudaGetSymbolAddress((void**)&h,     g_h);
    cudaGetSymbolAddress((void**)&h2pre, g_h2pre);
    cudaGetSymbolAddress((void**)&t2,    g_t2);
    int *deg, *offs, *cursor, *csr, *part;
    cudaGetSymbolAddress((void**)&deg,    g_deg);
    cudaGetSymbolAddress((void**)&offs,   g_offs);
    cudaGetSymbolAddress((void**)&cursor, g_cursor);
    cudaGetSymbolAddress((void**)&csr,    g_csr);
    cudaGetSymbolAddress((void**)&part,   g_part);

    float* out = (float*)d_out;
    const int rtiles      = (N + 63) / 64;
    const dim3 grid_w128(rtiles, 2);   // CO=128 -> 2 column blocks
    const dim3 grid_w64 (rtiles, 1);   // CO=64
    const int edge_blocks = (E + 255) / 256;
    const int scan_blocks = (N + SCAN_BS - 1) / SCAN_BS;
    const int g64_blocks  = (N * 16 + 255) / 256;
    const int g128_blocks = (N * 32 + 255) / 256;

    // ---- CSR build (shared by both layers) ----
    detect_idx_kernel<<<1, 32>>>((const unsigned*)ei);
    zero_kernel<<<(N + 255) / 256, 256>>>(deg, N);
    hist_kernel<<<edge_blocks, 256>>>(ei, deg, E);
    scan1_kernel<<<scan_blocks, SCAN_BS>>>(deg, offs, part, N);
    scan2_kernel<<<1, MAXPART>>>(part, offs, scan_blocks, N);
    scan3_kernel<<<scan_blocks, SCAN_BS>>>(offs, cursor, part, N);
    fill_kernel<<<edge_blocks, 256>>>(ei, cursor, csr, E);

    // ---- Layer 1 ----
    gather64_kernel<<<g64_blocks, 256>>>(x, offs, csr, h1pre, N);
    gemm_bias_kernel<CIN,  CHID, 1><<<grid_w128, 128>>>(h1pre, W1, b1, t1, N);
    gemm_bias_kernel<CHID, CHID, 1><<<grid_w128, 128>>>(t1,    W2, b2, h,  N);

    // ---- Layer 2 ----
    gather128_kernel<<<g128_blocks, 256>>>(h, offs, csr, h2pre, N);
    gemm_bias_kernel<CHID, CHID, 1><<<grid_w128, 128>>>(h2pre, W3, b3, t2,  N);
    gemm_bias_kernel<CHID, CIN,  0><<<grid_w64,  128>>>(t2,    W4, b4, out, N);
}

// round 8
// speedup vs baseline: 1.9254x; 1.1238x over previous
#include <cuda_runtime.h>
#include <cstdint>

// ---------------------------------------------------------------------------
// GIN (2 layers) on GB300 — CSR-gather aggregation + fused 2-GEMM MLP kernels.
// Each layer: one kernel computes relu(A@W1+b1) into SMEM (splatted k-major),
// then act(t@W2+b2) -> global. f32x2 FMA microkernel, cp.async W streaming.
// ---------------------------------------------------------------------------

#define NMAX 50000
#define EMAX 800000
#define CIN  64
#define CHID 128
#define SCAN_BS 1024
#define MAXPART 256

__device__ float g_h1pre[NMAX * CIN];
__device__ float g_h    [NMAX * CHID];
__device__ float g_h2pre[NMAX * CHID];

__device__ int g_deg   [NMAX];
__device__ int g_offs  [NMAX + 1];
__device__ int g_cursor[NMAX];
__device__ int g_csr   [EMAX];
__device__ int g_part  [MAXPART];
__device__ unsigned g_is64;

// ======================= small PTX helpers =================================
__device__ __forceinline__ uint32_t smem_u32(const void* p) {
    uint32_t a;
    asm("{ .reg .u64 t; cvta.to.shared.u64 t, %1; cvt.u32.u64 %0, t; }"
        : "=r"(a) : "l"(p));
    return a;
}
#define FMA2(acc_, a_, b_) \
    asm("fma.rn.f32x2 %0, %1, %2, %0;" : "+l"(acc_) : "l"(a_), "l"(b_))
#define UNPK(lo_, hi_, p_) \
    asm("mov.b64 {%0, %1}, %2;" : "=r"(lo_), "=r"(hi_) : "l"(p_))
#define CP_WAIT0() asm volatile("cp.async.wait_group 0;" ::: "memory")
#define CP_WAIT1() asm volatile("cp.async.wait_group 1;" ::: "memory")

// Stream one 32-row W block (32 x CO floats) into smem via cp.async.
template <int CO>
__device__ __forceinline__ void prefetch_w(uint32_t wb_dst, const float* __restrict__ Wsrc,
                                           int kb, int tid) {
    constexpr int IT = (32 * CO / 4) / 256;     // float4 per thread (4 or 2)
    const float* base = Wsrc + (long long)kb * 32 * CO;
#pragma unroll
    for (int t = 0; t < IT; ++t) {
        int idx = tid + t * 256;
        int row = idx / (CO / 4);
        int c4  = idx % (CO / 4);
        uint32_t dst = wb_dst + (uint32_t)(row * CO + c4 * 4) * 4u;
        const float* src = base + row * CO + c4 * 4;
        asm volatile("cp.async.cg.shared.global [%0], [%1], 16;" :: "r"(dst), "l"(src));
    }
    asm volatile("cp.async.commit_group;" ::: "memory");
}

// ======================= CSR build =========================================
__global__ void detect_idx_kernel(const unsigned* __restrict__ ei_u32) {
    if (threadIdx.x == 0 && blockIdx.x == 0) {
        unsigned acc = 0;
#pragma unroll 8
        for (int i = 0; i < 512; ++i) acc |= ei_u32[2 * i + 1];
        g_is64 = (acc == 0u) ? 1u : 0u;
    }
}
__global__ void zero_kernel(int* __restrict__ p, int n) {
    int i = blockIdx.x * blockDim.x + threadIdx.x;
    if (i < n) p[i] = 0;
}
__global__ void hist_kernel(const void* __restrict__ ei, int* __restrict__ deg, int E) {
    int e = blockIdx.x * blockDim.x + threadIdx.x;
    if (e >= E) return;
    int d = g_is64 ? (int)((const long long*)ei)[E + e] : ((const int*)ei)[E + e];
    atomicAdd(&deg[d], 1);
}
__global__ void scan1_kernel(const int* __restrict__ deg, int* __restrict__ offs,
                             int* __restrict__ part, int N) {
    __shared__ int wsum[32];
    const int tid = threadIdx.x, lane = tid & 31, wid = tid >> 5;
    int i = blockIdx.x * SCAN_BS + tid;
    int v = (i < N) ? deg[i] : 0;
    int x = v;
#pragma unroll
    for (int o = 1; o < 32; o <<= 1) {
        int y = __shfl_up_sync(0xffffffffu, x, o);
        if (lane >= o) x += y;
    }
    if (lane == 31) wsum[wid] = x;
    __syncthreads();
    if (wid == 0) {
        int w = wsum[lane];
#pragma unroll
        for (int o = 1; o < 32; o <<= 1) {
            int y = __shfl_up_sync(0xffffffffu, w, o);
            if (lane >= o) w += y;
        }
        wsum[lane] = w;
    }
    __syncthreads();
    int warpoff = (wid > 0) ? wsum[wid - 1] : 0;
    if (i < N) offs[i] = warpoff + x - v;
    if (tid == SCAN_BS - 1) part[blockIdx.x] = warpoff + x;
}
__global__ void scan2_kernel(int* __restrict__ part, int* __restrict__ offs,
                             int nblk, int N) {
    __shared__ int s[MAXPART];
    int tid = threadIdx.x;
    int v = (tid < nblk) ? part[tid] : 0;
    s[tid] = v;
    __syncthreads();
    for (int o = 1; o < MAXPART; o <<= 1) {
        int y = (tid >= o) ? s[tid - o] : 0;
        __syncthreads();
        s[tid] += y;
        __syncthreads();
    }
    if (tid < nblk) part[tid] = s[tid] - v;
    if (tid == MAXPART - 1) offs[N] = s[tid];
}
__global__ void scan3_kernel(int* __restrict__ offs, int* __restrict__ cursor,
                             const int* __restrict__ part, int N) {
    int i = blockIdx.x * SCAN_BS + threadIdx.x;
    if (i < N) {
        int v = offs[i] + part[blockIdx.x];
        offs[i] = v;
        cursor[i] = v;
    }
}
__global__ void fill_kernel(const void* __restrict__ ei, int* __restrict__ cursor,
                            int* __restrict__ csr, int E) {
    int e = blockIdx.x * blockDim.x + threadIdx.x;
    if (e >= E) return;
    int s, d;
    if (g_is64) {
        const long long* p = (const long long*)ei;
        s = (int)p[e];
        d = (int)p[E + e];
    } else {
        const int* p = (const int*)ei;
        s = p[e];
        d = p[E + e];
    }
    int pos = atomicAdd(&cursor[d], 1);
    csr[pos] = s;
}

// ======================= gathers ===========================================
__global__ void gather64_kernel(const float* __restrict__ feat,
                                const int* __restrict__ offs,
                                const int* __restrict__ csr,
                                float* __restrict__ out, int N) {
    int t = blockIdx.x * blockDim.x + threadIdx.x;
    int node = t >> 4;
    int lane = threadIdx.x & 15;
    if (node >= N) return;
    int s = offs[node], e = offs[node + 1];
    const float4* f4 = (const float4*)feat;
    float4 acc = f4[(long long)node * 16 + lane];
    int k = s;
    for (; k + 1 < e; k += 2) {
        int j0 = __ldg(&csr[k]);
        int j1 = __ldg(&csr[k + 1]);
        float4 v0 = f4[(long long)j0 * 16 + lane];
        float4 v1 = f4[(long long)j1 * 16 + lane];
        acc.x += v0.x + v1.x; acc.y += v0.y + v1.y;
        acc.z += v0.z + v1.z; acc.w += v0.w + v1.w;
    }
    if (k < e) {
        int j = __ldg(&csr[k]);
        float4 v = f4[(long long)j * 16 + lane];
        acc.x += v.x; acc.y += v.y; acc.z += v.z; acc.w += v.w;
    }
    ((float4*)out)[(long long)node * 16 + lane] = acc;
}
__global__ void gather128_kernel(const float* __restrict__ feat,
                                 const int* __restrict__ offs,
                                 const int* __restrict__ csr,
                                 float* __restrict__ out, int N) {
    int node = (int)((blockIdx.x * blockDim.x + threadIdx.x) >> 5);
    int lane = threadIdx.x & 31;
    if (node >= N) return;
    int s = offs[node], e = offs[node + 1];
    const float4* f4 = (const float4*)feat;
    float4 acc = f4[(long long)node * 32 + lane];
    int k = s;
    for (; k + 1 < e; k += 2) {
        int j0 = __ldg(&csr[k]);
        int j1 = __ldg(&csr[k + 1]);
        float4 v0 = f4[(long long)j0 * 32 + lane];
        float4 v1 = f4[(long long)j1 * 32 + lane];
        acc.x += v0.x + v1.x; acc.y += v0.y + v1.y;
        acc.z += v0.z + v1.z; acc.w += v0.w + v1.w;
    }
    if (k < e) {
        int j = __ldg(&csr[k]);
        float4 v = f4[(long long)j * 32 + lane];
        acc.x += v.x; acc.y += v.y; acc.z += v.z; acc.w += v.w;
    }
    ((float4*)out)[(long long)node * 32 + lane] = acc;
}

// ======================= fused 2-GEMM MLP ==================================
// Out[N,CO2] = act2(relu(A[N,CI] @ W1[CI,128] + b1) @ W2[128,CO2] + b2)
// One CTA per 64 rows, 256 threads (16 row-groups x 16 col-groups, TM=4).
// Stage-1 output lives in SMEM splatted k-major; W blocks stream via cp.async.
template <int CI, int CO2, int RELU2>
__global__ void __launch_bounds__(256, 1)
mlp_fused_kernel(const float* __restrict__ A,
                 const float* __restrict__ W1, const float* __restrict__ b1,
                 const float* __restrict__ W2, const float* __restrict__ b2,
                 float* __restrict__ Out, int Nrows) {
    constexpr int SA  = 132;           // splat row stride (floats), 16B-aligned
    constexpr int KB1 = CI / 32;       // stage-1 k-blocks (2 or 4)
    constexpr int KB2 = 128 / 32;      // stage-2 k-blocks
    constexpr int NG  = CO2 / 64;      // stage-2 column groups (2 or 1)

    extern __shared__ float sm[];
    float* As = sm;                    // CI x SA   (splatted input tile)
    float* T1 = As + CI * SA;          // 128 x SA  (splatted stage-1 output)
    float* Wb = T1 + 128 * SA;         // 2 x 32 x 128 (W double buffer)
    const uint32_t wb_addr = smem_u32(Wb);
    constexpr uint32_t WBUF_BYTES = 32 * 128 * 4;

    const int tid = threadIdx.x;
    const int tr  = tid >> 4;          // 0..15: rows tr*4..tr*4+3
    const int tc  = tid & 15;          // 0..15: cols tc*4 (+64 group)
    const long long rowBase = (long long)blockIdx.x * 64;

    // prefetch W1 block 0 ASAP
    prefetch_w<128>(wb_addr, W1, 0, tid);

    // ---- load A tile, splat-transpose into As ----
    constexpr int QA = CI / 4;
#pragma unroll
    for (int t = 0; t < 64 * QA / 256; ++t) {
        int idx = tid + t * 256;
        int m = idx / QA, q = idx % QA;
        long long row = rowBase + m;
        float4 v = make_float4(0.f, 0.f, 0.f, 0.f);
        if (row < Nrows) v = ((const float4*)(A + row * CI))[q];
        *(float2*)&As[(q * 4 + 0) * SA + 2 * m] = make_float2(v.x, v.x);
        *(float2*)&As[(q * 4 + 1) * SA + 2 * m] = make_float2(v.y, v.y);
        *(float2*)&As[(q * 4 + 2) * SA + 2 * m] = make_float2(v.z, v.z);
        *(float2*)&As[(q * 4 + 3) * SA + 2 * m] = make_float2(v.w, v.w);
    }

    unsigned long long acc[4][4];
#pragma unroll
    for (int i = 0; i < 4; ++i)
#pragma unroll
        for (int j = 0; j < 4; ++j) acc[i][j] = 0ull;

    // ---------------- stage 1: acc = A @ W1 ----------------
#pragma unroll
    for (int kb = 0; kb < KB1; ++kb) {
        if (kb + 1 < KB1) {
            prefetch_w<128>(wb_addr + ((kb + 1) & 1) * WBUF_BYTES, W1, kb + 1, tid);
            CP_WAIT1();
        } else {
            CP_WAIT0();
        }
        __syncthreads();                       // W block ready + As ready (kb=0)
        const float* Bs  = Wb + (kb & 1) * (32 * 128);
        const float* Asb = As + kb * 32 * SA;
#pragma unroll
        for (int k = 0; k < 32; ++k) {
            ulonglong2 aa = *(const ulonglong2*)&Asb[k * SA + tr * 8];
            ulonglong2 ab = *(const ulonglong2*)&Asb[k * SA + tr * 8 + 4];
            ulonglong2 b0 = *(const ulonglong2*)&Bs[k * 128 + tc * 4];
            ulonglong2 b1v = *(const ulonglong2*)&Bs[k * 128 + 64 + tc * 4];
            FMA2(acc[0][0], aa.x, b0.x); FMA2(acc[0][1], aa.x, b0.y);
            FMA2(acc[0][2], aa.x, b1v.x); FMA2(acc[0][3], aa.x, b1v.y);
            FMA2(acc[1][0], aa.y, b0.x); FMA2(acc[1][1], aa.y, b0.y);
            FMA2(acc[1][2], aa.y, b1v.x); FMA2(acc[1][3], aa.y, b1v.y);
            FMA2(acc[2][0], ab.x, b0.x); FMA2(acc[2][1], ab.x, b0.y);
            FMA2(acc[2][2], ab.x, b1v.x); FMA2(acc[2][3], ab.x, b1v.y);
            FMA2(acc[3][0], ab.y, b0.x); FMA2(acc[3][1], ab.y, b0.y);
            FMA2(acc[3][2], ab.y, b1v.x); FMA2(acc[3][3], ab.y, b1v.y);
        }
        __syncthreads();                       // all reads done before buffer reuse
    }

    // prefetch W2 block 0 (buf0 free: KB1 even -> last W1 block was in buf1)
    prefetch_w<CO2>(wb_addr, W2, 0, tid);

    // ---- stage-1 epilogue: bias + relu, splat into T1 ----
    {
        float bb[8];
#pragma unroll
        for (int e = 0; e < 4; ++e) {
            bb[e]     = __ldg(&b1[tc * 4 + e]);
            bb[4 + e] = __ldg(&b1[64 + tc * 4 + e]);
        }
#pragma unroll
        for (int i = 0; i < 4; ++i) {
            int m2 = 2 * (tr * 4 + i);
#pragma unroll
            for (int g = 0; g < 2; ++g)
#pragma unroll
                for (int jp = 0; jp < 2; ++jp) {
                    uint32_t lo, hi;
                    UNPK(lo, hi, acc[i][g * 2 + jp]);
                    float v0 = fmaxf(__uint_as_float(lo) + bb[g * 4 + jp * 2 + 0], 0.f);
                    float v1 = fmaxf(__uint_as_float(hi) + bb[g * 4 + jp * 2 + 1], 0.f);
                    int c = g * 64 + tc * 4 + jp * 2;
                    *(float2*)&T1[(c + 0) * SA + m2] = make_float2(v0, v0);
                    *(float2*)&T1[(c + 1) * SA + m2] = make_float2(v1, v1);
                }
        }
    }
    __syncthreads();                           // T1 complete

    // ---------------- stage 2: out = T1 @ W2 ----------------
    unsigned long long acc2[4][2 * NG];
#pragma unroll
    for (int i = 0; i < 4; ++i)
#pragma unroll
        for (int j = 0; j < 2 * NG; ++j) acc2[i][j] = 0ull;

#pragma unroll
    for (int kb = 0; kb < KB2; ++kb) {
        if (kb + 1 < KB2) {
            prefetch_w<CO2>(wb_addr + ((kb + 1) & 1) * WBUF_BYTES, W2, kb + 1, tid);
            CP_WAIT1();
        } else {
            CP_WAIT0();
        }
        __syncthreads();
        const float* Bs = Wb + (kb & 1) * (32 * 128);
        const float* Tb = T1 + kb * 32 * SA;
#pragma unroll
        for (int k = 0; k < 32; ++k) {
            ulonglong2 aa = *(const ulonglong2*)&Tb[k * SA + tr * 8];
            ulonglong2 ab = *(const ulonglong2*)&Tb[k * SA + tr * 8 + 4];
            ulonglong2 b0 = *(const ulonglong2*)&Bs[k * CO2 + tc * 4];
            FMA2(acc2[0][0], aa.x, b0.x); FMA2(acc2[0][1], aa.x, b0.y);
            FMA2(acc2[1][0], aa.y, b0.x); FMA2(acc2[1][1], aa.y, b0.y);
            FMA2(acc2[2][0], ab.x, b0.x); FMA2(acc2[2][1], ab.x, b0.y);
            FMA2(acc2[3][0], ab.y, b0.x); FMA2(acc2[3][1], ab.y, b0.y);
            if (NG == 2) {
                ulonglong2 b1v = *(const ulonglong2*)&Bs[k * CO2 + 64 + tc * 4];
                FMA2(acc2[0][2], aa.x, b1v.x); FMA2(acc2[0][3], aa.x, b1v.y);
                FMA2(acc2[1][2], aa.y, b1v.x); FMA2(acc2[1][3], aa.y, b1v.y);
                FMA2(acc2[2][2], ab.x, b1v.x); FMA2(acc2[2][3], ab.x, b1v.y);
                FMA2(acc2[3][2], ab.y, b1v.x); FMA2(acc2[3][3], ab.y, b1v.y);
            }
        }
        __syncthreads();
    }

    // ---- final epilogue: bias (+relu), STG.128 ----
    {
        float bb[4 * NG];
#pragma unroll
        for (int g = 0; g < NG; ++g)
#pragma unroll
            for (int e = 0; e < 4; ++e)
                bb[g * 4 + e] = __ldg(&b2[g * 64 + tc * 4 + e]);
#pragma unroll
        for (int i = 0; i < 4; ++i) {
            long long row = rowBase + tr * 4 + i;
            if (row >= Nrows) continue;
#pragma unroll
            for (int g = 0; g < NG; ++g) {
                uint32_t l0, h0, l1, h1;
                UNPK(l0, h0, acc2[i][g * 2 + 0]);
                UNPK(l1, h1, acc2[i][g * 2 + 1]);
                float4 o;
                o.x = __uint_as_float(l0) + bb[g * 4 + 0];
                o.y = __uint_as_float(h0) + bb[g * 4 + 1];
                o.z = __uint_as_float(l1) + bb[g * 4 + 2];
                o.w = __uint_as_float(h1) + bb[g * 4 + 3];
                if (RELU2) {
                    o.x = fmaxf(o.x, 0.f); o.y = fmaxf(o.y, 0.f);
                    o.z = fmaxf(o.z, 0.f); o.w = fmaxf(o.w, 0.f);
                }
                *(float4*)(Out + row * CO2 + g * 64 + tc * 4) = o;
            }
        }
    }
}

// ---------------------------------------------------------------------------
extern "C" void kernel_launch(void* const* d_in, const int* in_sizes, int n_in,
                              void* d_out, int out_size) {
    const float* x  = (const float*)d_in[0];
    const void*  ei = d_in[1];
    const float* W1 = (const float*)d_in[2];
    const float* b1 = (const float*)d_in[3];
    const float* W2 = (const float*)d_in[4];
    const float* b2 = (const float*)d_in[5];
    const float* W3 = (const float*)d_in[6];
    const float* b3 = (const float*)d_in[7];
    const float* W4 = (const float*)d_in[8];
    const float* b4 = (const float*)d_in[9];

    const int N = in_sizes[0] / CIN;
    const int E = in_sizes[1] / 2;

    float *h1pre, *h, *h2pre;
    cudaGetSymbolAddress((void**)&h1pre, g_h1pre);
    cudaGetSymbolAddress((void**)&h,     g_h);
    cudaGetSymbolAddress((void**)&h2pre, g_h2pre);
    int *deg, *offs, *cursor, *csr, *part;
    cudaGetSymbolAddress((void**)&deg,    g_deg);
    cudaGetSymbolAddress((void**)&offs,   g_offs);
    cudaGetSymbolAddress((void**)&cursor, g_cursor);
    cudaGetSymbolAddress((void**)&csr,    g_csr);
    cudaGetSymbolAddress((void**)&part,   g_part);

    float* out = (float*)d_out;
    const int rtiles      = (N + 63) / 64;
    const int edge_blocks = (E + 255) / 256;
    const int scan_blocks = (N + SCAN_BS - 1) / SCAN_BS;
    const int g64_blocks  = (N * 16 + 255) / 256;
    const int g128_blocks = (N * 32 + 255) / 256;

    // Dynamic smem sizes (floats -> bytes): As + T1 + W double buffer.
    const int smem_l1 = (CIN  * 132 + 128 * 132 + 2 * 32 * 128) * 4;   // ~131 KB
    const int smem_l2 = (CHID * 132 + 128 * 132 + 2 * 32 * 128) * 4;   // ~164 KB
    cudaFuncSetAttribute(mlp_fused_kernel<CIN,  CHID, 1>,
                         cudaFuncAttributeMaxDynamicSharedMemorySize, smem_l1);
    cudaFuncSetAttribute(mlp_fused_kernel<CHID, CIN,  0>,
                         cudaFuncAttributeMaxDynamicSharedMemorySize, smem_l2);

    // ---- CSR build (shared by both layers) ----
    detect_idx_kernel<<<1, 32>>>((const unsigned*)ei);
    zero_kernel<<<(N + 255) / 256, 256>>>(deg, N);
    hist_kernel<<<edge_blocks, 256>>>(ei, deg, E);
    scan1_kernel<<<scan_blocks, SCAN_BS>>>(deg, offs, part, N);
    scan2_kernel<<<1, MAXPART>>>(part, offs, scan_blocks, N);
    scan3_kernel<<<scan_blocks, SCAN_BS>>>(offs, cursor, part, N);
    fill_kernel<<<edge_blocks, 256>>>(ei, cursor, csr, E);

    // ---- Layer 1: gather + fused MLP (relu outer) ----
    gather64_kernel<<<g64_blocks, 256>>>(x, offs, csr, h1pre, N);
    mlp_fused_kernel<CIN,  CHID, 1><<<rtiles, 256, smem_l1>>>(h1pre, W1, b1, W2, b2, h, N);

    // ---- Layer 2: gather + fused MLP (no outer relu) ----
    gather128_kernel<<<g128_blocks, 256>>>(h, offs, csr, h2pre, N);
    mlp_fused_kernel<CHID, CIN,  0><<<rtiles, 256, smem_l2>>>(h2pre, W3, b3, W4, b4, out, N);
}

// round 9
// speedup vs baseline: 2.0863x; 1.0836x over previous
#include <cuda_runtime.h>
#include <cstdint>

// ---------------------------------------------------------------------------
// GIN (2 layers) on GB300 — CSR-gather aggregation + fused 2-GEMM MLP kernels.
// f32x2 (FFMA2) microkernels, cp.async W streaming, consolidated CSR build.
// ---------------------------------------------------------------------------

#define NMAX 50000
#define EMAX 800000
#define CIN  64
#define CHID 128
#define SCAN_BS 1024
#define MAXPART 256

__device__ float g_h1pre[NMAX * CIN];
__device__ float g_h    [NMAX * CHID];
__device__ float g_h2pre[NMAX * CHID];

__device__ int g_deg   [NMAX];
__device__ int g_offs  [NMAX + 1];
__device__ int g_cursor[NMAX];
__device__ int g_csr   [EMAX];
__device__ int g_part  [MAXPART];
__device__ unsigned g_is64;

// ======================= small PTX helpers =================================
__device__ __forceinline__ uint32_t smem_u32(const void* p) {
    uint32_t a;
    asm("{ .reg .u64 t; cvta.to.shared.u64 t, %1; cvt.u32.u64 %0, t; }"
        : "=r"(a) : "l"(p));
    return a;
}
#define FMA2(acc_, a_, b_) \
    asm("fma.rn.f32x2 %0, %1, %2, %0;" : "+l"(acc_) : "l"(a_), "l"(b_))
#define UNPK(lo_, hi_, p_) \
    asm("mov.b64 {%0, %1}, %2;" : "=r"(lo_), "=r"(hi_) : "l"(p_))
#define CP_WAIT0() asm volatile("cp.async.wait_group 0;" ::: "memory")
#define CP_WAIT1() asm volatile("cp.async.wait_group 1;" ::: "memory")

template <int CO>
__device__ __forceinline__ void prefetch_w(uint32_t wb_dst, const float* __restrict__ Wsrc,
                                           int kb, int tid) {
    constexpr int IT = (32 * CO / 4) / 256;
    const float* base = Wsrc + (long long)kb * 32 * CO;
#pragma unroll
    for (int t = 0; t < IT; ++t) {
        int idx = tid + t * 256;
        int row = idx / (CO / 4);
        int c4  = idx % (CO / 4);
        uint32_t dst = wb_dst + (uint32_t)(row * CO + c4 * 4) * 4u;
        const float* src = base + row * CO + c4 * 4;
        asm volatile("cp.async.cg.shared.global [%0], [%1], 16;" :: "r"(dst), "l"(src));
    }
    asm volatile("cp.async.commit_group;" ::: "memory");
}

// ======================= CSR build =========================================
// Fused: all blocks zero deg[]; last block's warp 0 detects index dtype.
__global__ void detect_zero_kernel(const unsigned* __restrict__ ei_u32,
                                   int* __restrict__ deg, int N) {
    int i = blockIdx.x * blockDim.x + threadIdx.x;
    if (i < N) deg[i] = 0;
    if (blockIdx.x == gridDim.x - 1 && threadIdx.x < 32) {
        unsigned acc = 0;
#pragma unroll
        for (int t = 0; t < 16; ++t)
            acc |= ei_u32[2 * (threadIdx.x + t * 32) + 1];
#pragma unroll
        for (int o = 16; o > 0; o >>= 1)
            acc |= __shfl_down_sync(0xffffffffu, acc, o);
        if (threadIdx.x == 0) g_is64 = (acc == 0u) ? 1u : 0u;
    }
}
__global__ void hist_kernel(const void* __restrict__ ei, int* __restrict__ deg, int E) {
    int e = blockIdx.x * blockDim.x + threadIdx.x;
    if (e >= E) return;
    int d = g_is64 ? (int)((const long long*)ei)[E + e] : ((const int*)ei)[E + e];
    atomicAdd(&deg[d], 1);
}
__global__ void scan1_kernel(const int* __restrict__ deg, int* __restrict__ offs,
                             int* __restrict__ part, int N) {
    __shared__ int wsum[32];
    const int tid = threadIdx.x, lane = tid & 31, wid = tid >> 5;
    int i = blockIdx.x * SCAN_BS + tid;
    int v = (i < N) ? deg[i] : 0;
    int x = v;
#pragma unroll
    for (int o = 1; o < 32; o <<= 1) {
        int y = __shfl_up_sync(0xffffffffu, x, o);
        if (lane >= o) x += y;
    }
    if (lane == 31) wsum[wid] = x;
    __syncthreads();
    if (wid == 0) {
        int w = wsum[lane];
#pragma unroll
        for (int o = 1; o < 32; o <<= 1) {
            int y = __shfl_up_sync(0xffffffffu, w, o);
            if (lane >= o) w += y;
        }
        wsum[lane] = w;
    }
    __syncthreads();
    int warpoff = (wid > 0) ? wsum[wid - 1] : 0;
    if (i < N) offs[i] = warpoff + x - v;
    if (tid == SCAN_BS - 1) part[blockIdx.x] = warpoff + x;
}
// Fused phases 2+3: each block computes its exclusive block offset by a
// strided warp reduction over part[0..blockIdx.x), then adds it in.
__global__ void scan23_kernel(int* __restrict__ offs, int* __restrict__ cursor,
                              const int* __restrict__ part, int nblk, int N) {
    __shared__ int soff;
    const int tid = threadIdx.x;
    if (tid < 32) {
        int s = 0;
        for (int j = tid; j < nblk; j += 32) {
            int pv = part[j];
            if (j < (int)blockIdx.x) s += pv;
            // last block also produces the grand total for offs[N]
            if (blockIdx.x == gridDim.x - 1) s += 0;  // (kept simple below)
        }
#pragma unroll
        for (int o = 16; o > 0; o >>= 1) s += __shfl_down_sync(0xffffffffu, s, o);
        if (tid == 0) soff = s;
    }
    __syncthreads();
    int i = blockIdx.x * SCAN_BS + tid;
    if (i < N) {
        int v = offs[i] + soff;
        offs[i] = v;
        cursor[i] = v;
    }
    // grand total: computed by last block's warp 0 (sum over ALL partials)
    if (blockIdx.x == gridDim.x - 1 && tid < 32) {
        int s = 0;
        for (int j = tid; j < nblk; j += 32) s += part[j];
#pragma unroll
        for (int o = 16; o > 0; o >>= 1) s += __shfl_down_sync(0xffffffffu, s, o);
        if (tid == 0) offs[N] = s;
    }
}
__global__ void fill_kernel(const void* __restrict__ ei, int* __restrict__ cursor,
                            int* __restrict__ csr, int E) {
    int e = blockIdx.x * blockDim.x + threadIdx.x;
    if (e >= E) return;
    int s, d;
    if (g_is64) {
        const long long* p = (const long long*)ei;
        s = (int)p[e];
        d = (int)p[E + e];
    } else {
        const int* p = (const int*)ei;
        s = p[e];
        d = p[E + e];
    }
    int pos = atomicAdd(&cursor[d], 1);
    csr[pos] = s;
}

// ======================= gathers (4x unrolled) =============================
__global__ void gather64_kernel(const float* __restrict__ feat,
                                const int* __restrict__ offs,
                                const int* __restrict__ csr,
                                float* __restrict__ out, int N) {
    int t = blockIdx.x * blockDim.x + threadIdx.x;
    int node = t >> 4;
    int lane = threadIdx.x & 15;
    if (node >= N) return;
    int s = offs[node], e = offs[node + 1];
    const float4* f4 = (const float4*)feat;
    float4 acc = f4[(long long)node * 16 + lane];
    int k = s;
    for (; k + 3 < e; k += 4) {
        int j0 = __ldg(&csr[k]);
        int j1 = __ldg(&csr[k + 1]);
        int j2 = __ldg(&csr[k + 2]);
        int j3 = __ldg(&csr[k + 3]);
        float4 v0 = f4[(long long)j0 * 16 + lane];
        float4 v1 = f4[(long long)j1 * 16 + lane];
        float4 v2 = f4[(long long)j2 * 16 + lane];
        float4 v3 = f4[(long long)j3 * 16 + lane];
        acc.x += (v0.x + v1.x) + (v2.x + v3.x);
        acc.y += (v0.y + v1.y) + (v2.y + v3.y);
        acc.z += (v0.z + v1.z) + (v2.z + v3.z);
        acc.w += (v0.w + v1.w) + (v2.w + v3.w);
    }
    for (; k < e; ++k) {
        int j = __ldg(&csr[k]);
        float4 v = f4[(long long)j * 16 + lane];
        acc.x += v.x; acc.y += v.y; acc.z += v.z; acc.w += v.w;
    }
    ((float4*)out)[(long long)node * 16 + lane] = acc;
}
__global__ void gather128_kernel(const float* __restrict__ feat,
                                 const int* __restrict__ offs,
                                 const int* __restrict__ csr,
                                 float* __restrict__ out, int N) {
    int node = (int)((blockIdx.x * blockDim.x + threadIdx.x) >> 5);
    int lane = threadIdx.x & 31;
    if (node >= N) return;
    int s = offs[node], e = offs[node + 1];
    const float4* f4 = (const float4*)feat;
    float4 acc = f4[(long long)node * 32 + lane];
    int k = s;
    for (; k + 3 < e; k += 4) {
        int j0 = __ldg(&csr[k]);
        int j1 = __ldg(&csr[k + 1]);
        int j2 = __ldg(&csr[k + 2]);
        int j3 = __ldg(&csr[k + 3]);
        float4 v0 = f4[(long long)j0 * 32 + lane];
        float4 v1 = f4[(long long)j1 * 32 + lane];
        float4 v2 = f4[(long long)j2 * 32 + lane];
        float4 v3 = f4[(long long)j3 * 32 + lane];
        acc.x += (v0.x + v1.x) + (v2.x + v3.x);
        acc.y += (v0.y + v1.y) + (v2.y + v3.y);
        acc.z += (v0.z + v1.z) + (v2.z + v3.z);
        acc.w += (v0.w + v1.w) + (v2.w + v3.w);
    }
    for (; k < e; ++k) {
        int j = __ldg(&csr[k]);
        float4 v = f4[(long long)j * 32 + lane];
        acc.x += v.x; acc.y += v.y; acc.z += v.z; acc.w += v.w;
    }
    ((float4*)out)[(long long)node * 32 + lane] = acc;
}

// ======================= fused 2-GEMM MLP ==================================
template <int CI, int CO2, int RELU2>
__global__ void __launch_bounds__(256, 1)
mlp_fused_kernel(const float* __restrict__ A,
                 const float* __restrict__ W1, const float* __restrict__ b1,
                 const float* __restrict__ W2, const float* __restrict__ b2,
                 float* __restrict__ Out, int Nrows) {
    constexpr int SA  = 132;
    constexpr int KB1 = CI / 32;
    constexpr int KB2 = 128 / 32;
    constexpr int NG  = CO2 / 64;

    extern __shared__ float sm[];
    float* As = sm;
    float* T1 = As + CI * SA;
    float* Wb = T1 + 128 * SA;
    const uint32_t wb_addr = smem_u32(Wb);
    constexpr uint32_t WBUF_BYTES = 32 * 128 * 4;

    const int tid = threadIdx.x;
    const int tr  = tid >> 4;
    const int tc  = tid & 15;
    const long long rowBase = (long long)blockIdx.x * 64;

    prefetch_w<128>(wb_addr, W1, 0, tid);

    constexpr int QA = CI / 4;
#pragma unroll
    for (int t = 0; t < 64 * QA / 256; ++t) {
        int idx = tid + t * 256;
        int m = idx / QA, q = idx % QA;
        long long row = rowBase + m;
        float4 v = make_float4(0.f, 0.f, 0.f, 0.f);
        if (row < Nrows) v = ((const float4*)(A + row * CI))[q];
        *(float2*)&As[(q * 4 + 0) * SA + 2 * m] = make_float2(v.x, v.x);
        *(float2*)&As[(q * 4 + 1) * SA + 2 * m] = make_float2(v.y, v.y);
        *(float2*)&As[(q * 4 + 2) * SA + 2 * m] = make_float2(v.z, v.z);
        *(float2*)&As[(q * 4 + 3) * SA + 2 * m] = make_float2(v.w, v.w);
    }

    unsigned long long acc[4][4];
#pragma unroll
    for (int i = 0; i < 4; ++i)
#pragma unroll
        for (int j = 0; j < 4; ++j) acc[i][j] = 0ull;

    // ---------------- stage 1: acc = A @ W1 ----------------
#pragma unroll
    for (int kb = 0; kb < KB1; ++kb) {
        if (kb + 1 < KB1) {
            prefetch_w<128>(wb_addr + ((kb + 1) & 1) * WBUF_BYTES, W1, kb + 1, tid);
            CP_WAIT1();
        } else {
            CP_WAIT0();
        }
        __syncthreads();
        const float* Bs  = Wb + (kb & 1) * (32 * 128);
        const float* Asb = As + kb * 32 * SA;
#pragma unroll
        for (int k = 0; k < 32; ++k) {
            ulonglong2 aa = *(const ulonglong2*)&Asb[k * SA + tr * 8];
            ulonglong2 ab = *(const ulonglong2*)&Asb[k * SA + tr * 8 + 4];
            ulonglong2 b0 = *(const ulonglong2*)&Bs[k * 128 + tc * 4];
            ulonglong2 b1v = *(const ulonglong2*)&Bs[k * 128 + 64 + tc * 4];
            FMA2(acc[0][0], aa.x, b0.x); FMA2(acc[0][1], aa.x, b0.y);
            FMA2(acc[0][2], aa.x, b1v.x); FMA2(acc[0][3], aa.x, b1v.y);
            FMA2(acc[1][0], aa.y, b0.x); FMA2(acc[1][1], aa.y, b0.y);
            FMA2(acc[1][2], aa.y, b1v.x); FMA2(acc[1][3], aa.y, b1v.y);
            FMA2(acc[2][0], ab.x, b0.x); FMA2(acc[2][1], ab.x, b0.y);
            FMA2(acc[2][2], ab.x, b1v.x); FMA2(acc[2][3], ab.x, b1v.y);
            FMA2(acc[3][0], ab.y, b0.x); FMA2(acc[3][1], ab.y, b0.y);
            FMA2(acc[3][2], ab.y, b1v.x); FMA2(acc[3][3], ab.y, b1v.y);
        }
        __syncthreads();
    }

    prefetch_w<CO2>(wb_addr, W2, 0, tid);

    // ---- stage-1 epilogue: bias + relu, splat into T1 ----
    {
        float bb[8];
#pragma unroll
        for (int e = 0; e < 4; ++e) {
            bb[e]     = __ldg(&b1[tc * 4 + e]);
            bb[4 + e] = __ldg(&b1[64 + tc * 4 + e]);
        }
#pragma unroll
        for (int i = 0; i < 4; ++i) {
            int m2 = 2 * (tr * 4 + i);
#pragma unroll
            for (int g = 0; g < 2; ++g)
#pragma unroll
                for (int jp = 0; jp < 2; ++jp) {
                    uint32_t lo, hi;
                    UNPK(lo, hi, acc[i][g * 2 + jp]);
                    float v0 = fmaxf(__uint_as_float(lo) + bb[g * 4 + jp * 2 + 0], 0.f);
                    float v1 = fmaxf(__uint_as_float(hi) + bb[g * 4 + jp * 2 + 1], 0.f);
                    int c = g * 64 + tc * 4 + jp * 2;
                    *(float2*)&T1[(c + 0) * SA + m2] = make_float2(v0, v0);
                    *(float2*)&T1[(c + 1) * SA + m2] = make_float2(v1, v1);
                }
        }
    }
    __syncthreads();

    // ---------------- stage 2: out = T1 @ W2 ----------------
    unsigned long long acc2[4][2 * NG];
#pragma unroll
    for (int i = 0; i < 4; ++i)
#pragma unroll
        for (int j = 0; j < 2 * NG; ++j) acc2[i][j] = 0ull;

#pragma unroll
    for (int kb = 0; kb < KB2; ++kb) {
        if (kb + 1 < KB2) {
            prefetch_w<CO2>(wb_addr + ((kb + 1) & 1) * WBUF_BYTES, W2, kb + 1, tid);
            CP_WAIT1();
        } else {
            CP_WAIT0();
        }
        __syncthreads();
        const float* Bs = Wb + (kb & 1) * (32 * 128);
        const float* Tb = T1 + kb * 32 * SA;
#pragma unroll
        for (int k = 0; k < 32; ++k) {
            ulonglong2 aa = *(const ulonglong2*)&Tb[k * SA + tr * 8];
            ulonglong2 ab = *(const ulonglong2*)&Tb[k * SA + tr * 8 + 4];
            ulonglong2 b0 = *(const ulonglong2*)&Bs[k * CO2 + tc * 4];
            FMA2(acc2[0][0], aa.x, b0.x); FMA2(acc2[0][1], aa.x, b0.y);
            FMA2(acc2[1][0], aa.y, b0.x); FMA2(acc2[1][1], aa.y, b0.y);
            FMA2(acc2[2][0], ab.x, b0.x); FMA2(acc2[2][1], ab.x, b0.y);
            FMA2(acc2[3][0], ab.y, b0.x); FMA2(acc2[3][1], ab.y, b0.y);
            if (NG == 2) {
                ulonglong2 b1v = *(const ulonglong2*)&Bs[k * CO2 + 64 + tc * 4];
                FMA2(acc2[0][2], aa.x, b1v.x); FMA2(acc2[0][3], aa.x, b1v.y);
                FMA2(acc2[1][2], aa.y, b1v.x); FMA2(acc2[1][3], aa.y, b1v.y);
                FMA2(acc2[2][2], ab.x, b1v.x); FMA2(acc2[2][3], ab.x, b1v.y);
                FMA2(acc2[3][2], ab.y, b1v.x); FMA2(acc2[3][3], ab.y, b1v.y);
            }
        }
        __syncthreads();
    }

    // ---- final epilogue ----
    {
        float bb[4 * NG];
#pragma unroll
        for (int g = 0; g < NG; ++g)
#pragma unroll
            for (int e = 0; e < 4; ++e)
                bb[g * 4 + e] = __ldg(&b2[g * 64 + tc * 4 + e]);
#pragma unroll
        for (int i = 0; i < 4; ++i) {
            long long row = rowBase + tr * 4 + i;
            if (row >= Nrows) continue;
#pragma unroll
            for (int g = 0; g < NG; ++g) {
                uint32_t l0, h0, l1, h1;
                UNPK(l0, h0, acc2[i][g * 2 + 0]);
                UNPK(l1, h1, acc2[i][g * 2 + 1]);
                float4 o;
                o.x = __uint_as_float(l0) + bb[g * 4 + 0];
                o.y = __uint_as_float(h0) + bb[g * 4 + 1];
                o.z = __uint_as_float(l1) + bb[g * 4 + 2];
                o.w = __uint_as_float(h1) + bb[g * 4 + 3];
                if (RELU2) {
                    o.x = fmaxf(o.x, 0.f); o.y = fmaxf(o.y, 0.f);
                    o.z = fmaxf(o.z, 0.f); o.w = fmaxf(o.w, 0.f);
                }
                *(float4*)(Out + row * CO2 + g * 64 + tc * 4) = o;
            }
        }
    }
}

// ---------------------------------------------------------------------------
extern "C" void kernel_launch(void* const* d_in, const int* in_sizes, int n_in,
                              void* d_out, int out_size) {
    const float* x  = (const float*)d_in[0];
    const void*  ei = d_in[1];
    const float* W1 = (const float*)d_in[2];
    const float* b1 = (const float*)d_in[3];
    const float* W2 = (const float*)d_in[4];
    const float* b2 = (const float*)d_in[5];
    const float* W3 = (const float*)d_in[6];
    const float* b3 = (const float*)d_in[7];
    const float* W4 = (const float*)d_in[8];
    const float* b4 = (const float*)d_in[9];

    const int N = in_sizes[0] / CIN;
    const int E = in_sizes[1] / 2;

    float *h1pre, *h, *h2pre;
    cudaGetSymbolAddress((void**)&h1pre, g_h1pre);
    cudaGetSymbolAddress((void**)&h,     g_h);
    cudaGetSymbolAddress((void**)&h2pre, g_h2pre);
    int *deg, *offs, *cursor, *csr, *part;
    cudaGetSymbolAddress((void**)&deg,    g_deg);
    cudaGetSymbolAddress((void**)&offs,   g_offs);
    cudaGetSymbolAddress((void**)&cursor, g_cursor);
    cudaGetSymbolAddress((void**)&csr,    g_csr);
    cudaGetSymbolAddress((void**)&part,   g_part);

    float* out = (float*)d_out;
    const int rtiles      = (N + 63) / 64;
    const int edge_blocks = (E + 255) / 256;
    const int scan_blocks = (N + SCAN_BS - 1) / SCAN_BS;
    const int g64_blocks  = (N * 16 + 255) / 256;
    const int g128_blocks = (N * 32 + 255) / 256;

    const int smem_l1 = (CIN  * 132 + 128 * 132 + 2 * 32 * 128) * 4;
    const int smem_l2 = (CHID * 132 + 128 * 132 + 2 * 32 * 128) * 4;
    cudaFuncSetAttribute(mlp_fused_kernel<CIN,  CHID, 1>,
                         cudaFuncAttributeMaxDynamicSharedMemorySize, smem_l1);
    cudaFuncSetAttribute(mlp_fused_kernel<CHID, CIN,  0>,
                         cudaFuncAttributeMaxDynamicSharedMemorySize, smem_l2);

    // ---- CSR build (5 launches) ----
    detect_zero_kernel<<<(N + 255) / 256, 256>>>((const unsigned*)ei, deg, N);
    hist_kernel<<<edge_blocks, 256>>>(ei, deg, E);
    scan1_kernel<<<scan_blocks, SCAN_BS>>>(deg, offs, part, N);
    scan23_kernel<<<scan_blocks, SCAN_BS>>>(offs, cursor, part, scan_blocks, N);
    fill_kernel<<<edge_blocks, 256>>>(ei, cursor, csr, E);

    // ---- Layer 1 ----
    gather64_kernel<<<g64_blocks, 256>>>(x, offs, csr, h1pre, N);
    mlp_fused_kernel<CIN,  CHID, 1><<<rtiles, 256, smem_l1>>>(h1pre, W1, b1, W2, b2, h, N);

    // ---- Layer 2 ----
    gather128_kernel<<<g128_blocks, 256>>>(h, offs, csr, h2pre, N);
    mlp_fused_kernel<CHID, CIN,  0><<<rtiles, 256, smem_l2>>>(h2pre, W3, b3, W4, b4, out, N);
}

// round 10
// speedup vs baseline: 2.1758x; 1.0429x over previous
#include <cuda_runtime.h>
#include <cstdint>

// ---------------------------------------------------------------------------
// GIN (2 layers) on GB300 — CSR-gather aggregation + fused 2-GEMM MLP kernels.
// f32x2 (FFMA2) microkernels, cp.async W streaming, As/T1 SMEM aliasing for
// 2 CTAs/SM occupancy.
// ---------------------------------------------------------------------------

#define NMAX 50000
#define EMAX 800000
#define CIN  64
#define CHID 128
#define SCAN_BS 1024
#define MAXPART 256

__device__ float g_h1pre[NMAX * CIN];
__device__ float g_h    [NMAX * CHID];
__device__ float g_h2pre[NMAX * CHID];

__device__ int g_deg   [NMAX];
__device__ int g_offs  [NMAX + 1];
__device__ int g_cursor[NMAX];
__device__ int g_csr   [EMAX];
__device__ int g_part  [MAXPART];
__device__ unsigned g_is64;

// ======================= small PTX helpers =================================
__device__ __forceinline__ uint32_t smem_u32(const void* p) {
    uint32_t a;
    asm("{ .reg .u64 t; cvta.to.shared.u64 t, %1; cvt.u32.u64 %0, t; }"
        : "=r"(a) : "l"(p));
    return a;
}
#define FMA2(acc_, a_, b_) \
    asm("fma.rn.f32x2 %0, %1, %2, %0;" : "+l"(acc_) : "l"(a_), "l"(b_))
#define UNPK(lo_, hi_, p_) \
    asm("mov.b64 {%0, %1}, %2;" : "=r"(lo_), "=r"(hi_) : "l"(p_))
#define CP_WAIT0() asm volatile("cp.async.wait_group 0;" ::: "memory")
#define CP_WAIT1() asm volatile("cp.async.wait_group 1;" ::: "memory")

template <int CO>
__device__ __forceinline__ void prefetch_w(uint32_t wb_dst, const float* __restrict__ Wsrc,
                                           int kb, int tid) {
    constexpr int IT = (32 * CO / 4) / 256;
    const float* base = Wsrc + (long long)kb * 32 * CO;
#pragma unroll
    for (int t = 0; t < IT; ++t) {
        int idx = tid + t * 256;
        int row = idx / (CO / 4);
        int c4  = idx % (CO / 4);
        uint32_t dst = wb_dst + (uint32_t)(row * CO + c4 * 4) * 4u;
        const float* src = base + row * CO + c4 * 4;
        asm volatile("cp.async.cg.shared.global [%0], [%1], 16;" :: "r"(dst), "l"(src));
    }
    asm volatile("cp.async.commit_group;" ::: "memory");
}

// ======================= CSR build =========================================
__global__ void detect_zero_kernel(const unsigned* __restrict__ ei_u32,
                                   int* __restrict__ deg, int N) {
    int i = blockIdx.x * blockDim.x + threadIdx.x;
    if (i < N) deg[i] = 0;
    if (blockIdx.x == gridDim.x - 1 && threadIdx.x < 32) {
        unsigned acc = 0;
#pragma unroll
        for (int t = 0; t < 16; ++t)
            acc |= ei_u32[2 * (threadIdx.x + t * 32) + 1];
#pragma unroll
        for (int o = 16; o > 0; o >>= 1)
            acc |= __shfl_down_sync(0xffffffffu, acc, o);
        if (threadIdx.x == 0) g_is64 = (acc == 0u) ? 1u : 0u;
    }
}
__global__ void hist_kernel(const void* __restrict__ ei, int* __restrict__ deg, int E) {
    int e = blockIdx.x * blockDim.x + threadIdx.x;
    if (e >= E) return;
    int d = g_is64 ? (int)((const long long*)ei)[E + e] : ((const int*)ei)[E + e];
    atomicAdd(&deg[d], 1);
}
__global__ void scan1_kernel(const int* __restrict__ deg, int* __restrict__ offs,
                             int* __restrict__ part, int N) {
    __shared__ int wsum[32];
    const int tid = threadIdx.x, lane = tid & 31, wid = tid >> 5;
    int i = blockIdx.x * SCAN_BS + tid;
    int v = (i < N) ? deg[i] : 0;
    int x = v;
#pragma unroll
    for (int o = 1; o < 32; o <<= 1) {
        int y = __shfl_up_sync(0xffffffffu, x, o);
        if (lane >= o) x += y;
    }
    if (lane == 31) wsum[wid] = x;
    __syncthreads();
    if (wid == 0) {
        int w = wsum[lane];
#pragma unroll
        for (int o = 1; o < 32; o <<= 1) {
            int y = __shfl_up_sync(0xffffffffu, w, o);
            if (lane >= o) w += y;
        }
        wsum[lane] = w;
    }
    __syncthreads();
    int warpoff = (wid > 0) ? wsum[wid - 1] : 0;
    if (i < N) offs[i] = warpoff + x - v;
    if (tid == SCAN_BS - 1) part[blockIdx.x] = warpoff + x;
}
__global__ void scan23_kernel(int* __restrict__ offs, int* __restrict__ cursor,
                              const int* __restrict__ part, int nblk, int N) {
    __shared__ int soff;
    const int tid = threadIdx.x;
    if (tid < 32) {
        int s = 0;
        for (int j = tid; j < nblk; j += 32)
            if (j < (int)blockIdx.x) s += part[j];
#pragma unroll
        for (int o = 16; o > 0; o >>= 1) s += __shfl_down_sync(0xffffffffu, s, o);
        if (tid == 0) soff = s;
    }
    __syncthreads();
    int i = blockIdx.x * SCAN_BS + tid;
    if (i < N) {
        int v = offs[i] + soff;
        offs[i] = v;
        cursor[i] = v;
    }
    if (blockIdx.x == gridDim.x - 1 && tid < 32) {
        int s = 0;
        for (int j = tid; j < nblk; j += 32) s += part[j];
#pragma unroll
        for (int o = 16; o > 0; o >>= 1) s += __shfl_down_sync(0xffffffffu, s, o);
        if (tid == 0) offs[N] = s;
    }
}
__global__ void fill_kernel(const void* __restrict__ ei, int* __restrict__ cursor,
                            int* __restrict__ csr, int E) {
    int e = blockIdx.x * blockDim.x + threadIdx.x;
    if (e >= E) return;
    int s, d;
    if (g_is64) {
        const long long* p = (const long long*)ei;
        s = (int)p[e];
        d = (int)p[E + e];
    } else {
        const int* p = (const int*)ei;
        s = p[e];
        d = p[E + e];
    }
    int pos = atomicAdd(&cursor[d], 1);
    csr[pos] = s;
}

// ======================= gathers (4x unrolled) =============================
__global__ void gather64_kernel(const float* __restrict__ feat,
                                const int* __restrict__ offs,
                                const int* __restrict__ csr,
                                float* __restrict__ out, int N) {
    int t = blockIdx.x * blockDim.x + threadIdx.x;
    int node = t >> 4;
    int lane = threadIdx.x & 15;
    if (node >= N) return;
    int s = offs[node], e = offs[node + 1];
    const float4* f4 = (const float4*)feat;
    float4 acc = f4[(long long)node * 16 + lane];
    int k = s;
    for (; k + 3 < e; k += 4) {
        int j0 = __ldg(&csr[k]);
        int j1 = __ldg(&csr[k + 1]);
        int j2 = __ldg(&csr[k + 2]);
        int j3 = __ldg(&csr[k + 3]);
        float4 v0 = f4[(long long)j0 * 16 + lane];
        float4 v1 = f4[(long long)j1 * 16 + lane];
        float4 v2 = f4[(long long)j2 * 16 + lane];
        float4 v3 = f4[(long long)j3 * 16 + lane];
        acc.x += (v0.x + v1.x) + (v2.x + v3.x);
        acc.y += (v0.y + v1.y) + (v2.y + v3.y);
        acc.z += (v0.z + v1.z) + (v2.z + v3.z);
        acc.w += (v0.w + v1.w) + (v2.w + v3.w);
    }
    for (; k < e; ++k) {
        int j = __ldg(&csr[k]);
        float4 v = f4[(long long)j * 16 + lane];
        acc.x += v.x; acc.y += v.y; acc.z += v.z; acc.w += v.w;
    }
    ((float4*)out)[(long long)node * 16 + lane] = acc;
}
__global__ void gather128_kernel(const float* __restrict__ feat,
                                 const int* __restrict__ offs,
                                 const int* __restrict__ csr,
                                 float* __restrict__ out, int N) {
    int node = (int)((blockIdx.x * blockDim.x + threadIdx.x) >> 5);
    int lane = threadIdx.x & 31;
    if (node >= N) return;
    int s = offs[node], e = offs[node + 1];
    const float4* f4 = (const float4*)feat;
    float4 acc = f4[(long long)node * 32 + lane];
    int k = s;
    for (; k + 3 < e; k += 4) {
        int j0 = __ldg(&csr[k]);
        int j1 = __ldg(&csr[k + 1]);
        int j2 = __ldg(&csr[k + 2]);
        int j3 = __ldg(&csr[k + 3]);
        float4 v0 = f4[(long long)j0 * 32 + lane];
        float4 v1 = f4[(long long)j1 * 32 + lane];
        float4 v2 = f4[(long long)j2 * 32 + lane];
        float4 v3 = f4[(long long)j3 * 32 + lane];
        acc.x += (v0.x + v1.x) + (v2.x + v3.x);
        acc.y += (v0.y + v1.y) + (v2.y + v3.y);
        acc.z += (v0.z + v1.z) + (v2.z + v3.z);
        acc.w += (v0.w + v1.w) + (v2.w + v3.w);
    }
    for (; k < e; ++k) {
        int j = __ldg(&csr[k]);
        float4 v = f4[(long long)j * 32 + lane];
        acc.x += v.x; acc.y += v.y; acc.z += v.z; acc.w += v.w;
    }
    ((float4*)out)[(long long)node * 32 + lane] = acc;
}

// ======================= fused 2-GEMM MLP ==================================
// Out[N,CO2] = act2(relu(A[N,CI] @ W1[CI,128] + b1) @ W2[128,CO2] + b2)
// As (stage-1 input, CI x SA) and T1 (stage-1 output, 128 x SA) ALIAS the same
// SMEM buffer: As is dead after the stage-1 mainloop's final syncthreads, T1
// is written only in the stage-1 epilogue. 100KB smem -> 2 CTAs/SM.
template <int CI, int CO2, int RELU2>
__global__ void __launch_bounds__(256, 2)
mlp_fused_kernel(const float* __restrict__ A,
                 const float* __restrict__ W1, const float* __restrict__ b1,
                 const float* __restrict__ W2, const float* __restrict__ b2,
                 float* __restrict__ Out, int Nrows) {
    constexpr int SA  = 132;
    constexpr int KB1 = CI / 32;
    constexpr int KB2 = 128 / 32;
    constexpr int NG  = CO2 / 64;

    extern __shared__ float sm[];
    float* As = sm;                    // CI x SA   (aliases T1)
    float* T1 = sm;                    // 128 x SA  (written after As is dead)
    float* Wb = sm + 128 * SA;         // 2 x 32 x 128 W double buffer
    const uint32_t wb_addr = smem_u32(Wb);
    constexpr uint32_t WBUF_BYTES = 32 * 128 * 4;

    const int tid = threadIdx.x;
    const int tr  = tid >> 4;
    const int tc  = tid & 15;
    const long long rowBase = (long long)blockIdx.x * 64;

    prefetch_w<128>(wb_addr, W1, 0, tid);

    constexpr int QA = CI / 4;
#pragma unroll
    for (int t = 0; t < 64 * QA / 256; ++t) {
        int idx = tid + t * 256;
        int m = idx / QA, q = idx % QA;
        long long row = rowBase + m;
        float4 v = make_float4(0.f, 0.f, 0.f, 0.f);
        if (row < Nrows) v = ((const float4*)(A + row * CI))[q];
        *(float2*)&As[(q * 4 + 0) * SA + 2 * m] = make_float2(v.x, v.x);
        *(float2*)&As[(q * 4 + 1) * SA + 2 * m] = make_float2(v.y, v.y);
        *(float2*)&As[(q * 4 + 2) * SA + 2 * m] = make_float2(v.z, v.z);
        *(float2*)&As[(q * 4 + 3) * SA + 2 * m] = make_float2(v.w, v.w);
    }

    unsigned long long acc[4][4];
#pragma unroll
    for (int i = 0; i < 4; ++i)
#pragma unroll
        for (int j = 0; j < 4; ++j) acc[i][j] = 0ull;

    // ---------------- stage 1: acc = A @ W1 ----------------
#pragma unroll
    for (int kb = 0; kb < KB1; ++kb) {
        if (kb + 1 < KB1) {
            prefetch_w<128>(wb_addr + ((kb + 1) & 1) * WBUF_BYTES, W1, kb + 1, tid);
            CP_WAIT1();
        } else {
            CP_WAIT0();
        }
        __syncthreads();
        const float* Bs  = Wb + (kb & 1) * (32 * 128);
        const float* Asb = As + kb * 32 * SA;
#pragma unroll
        for (int k = 0; k < 32; ++k) {
            ulonglong2 aa = *(const ulonglong2*)&Asb[k * SA + tr * 8];
            ulonglong2 ab = *(const ulonglong2*)&Asb[k * SA + tr * 8 + 4];
            ulonglong2 b0 = *(const ulonglong2*)&Bs[k * 128 + tc * 4];
            ulonglong2 b1v = *(const ulonglong2*)&Bs[k * 128 + 64 + tc * 4];
            FMA2(acc[0][0], aa.x, b0.x); FMA2(acc[0][1], aa.x, b0.y);
            FMA2(acc[0][2], aa.x, b1v.x); FMA2(acc[0][3], aa.x, b1v.y);
            FMA2(acc[1][0], aa.y, b0.x); FMA2(acc[1][1], aa.y, b0.y);
            FMA2(acc[1][2], aa.y, b1v.x); FMA2(acc[1][3], aa.y, b1v.y);
            FMA2(acc[2][0], ab.x, b0.x); FMA2(acc[2][1], ab.x, b0.y);
            FMA2(acc[2][2], ab.x, b1v.x); FMA2(acc[2][3], ab.x, b1v.y);
            FMA2(acc[3][0], ab.y, b0.x); FMA2(acc[3][1], ab.y, b0.y);
            FMA2(acc[3][2], ab.y, b1v.x); FMA2(acc[3][3], ab.y, b1v.y);
        }
        __syncthreads();   // all As reads done -> safe to overwrite (T1 alias)
    }

    prefetch_w<CO2>(wb_addr, W2, 0, tid);

    // ---- stage-1 epilogue: bias + relu, splat into T1 (aliasing As) ----
    {
        float bb[8];
#pragma unroll
        for (int e = 0; e < 4; ++e) {
            bb[e]     = __ldg(&b1[tc * 4 + e]);
            bb[4 + e] = __ldg(&b1[64 + tc * 4 + e]);
        }
#pragma unroll
        for (int i = 0; i < 4; ++i) {
            int m2 = 2 * (tr * 4 + i);
#pragma unroll
            for (int g = 0; g < 2; ++g)
#pragma unroll
                for (int jp = 0; jp < 2; ++jp) {
                    uint32_t lo, hi;
                    UNPK(lo, hi, acc[i][g * 2 + jp]);
                    float v0 = fmaxf(__uint_as_float(lo) + bb[g * 4 + jp * 2 + 0], 0.f);
                    float v1 = fmaxf(__uint_as_float(hi) + bb[g * 4 + jp * 2 + 1], 0.f);
                    int c = g * 64 + tc * 4 + jp * 2;
                    *(float2*)&T1[(c + 0) * SA + m2] = make_float2(v0, v0);
                    *(float2*)&T1[(c + 1) * SA + m2] = make_float2(v1, v1);
                }
        }
    }
    __syncthreads();

    // ---------------- stage 2: out = T1 @ W2 ----------------
    unsigned long long acc2[4][2 * NG];
#pragma unroll
    for (int i = 0; i < 4; ++i)
#pragma unroll
        for (int j = 0; j < 2 * NG; ++j) acc2[i][j] = 0ull;

#pragma unroll
    for (int kb = 0; kb < KB2; ++kb) {
        if (kb + 1 < KB2) {
            prefetch_w<CO2>(wb_addr + ((kb + 1) & 1) * WBUF_BYTES, W2, kb + 1, tid);
            CP_WAIT1();
        } else {
            CP_WAIT0();
        }
        __syncthreads();
        const float* Bs = Wb + (kb & 1) * (32 * 128);
        const float* Tb = T1 + kb * 32 * SA;
#pragma unroll
        for (int k = 0; k < 32; ++k) {
            ulonglong2 aa = *(const ulonglong2*)&Tb[k * SA + tr * 8];
            ulonglong2 ab = *(const ulonglong2*)&Tb[k * SA + tr * 8 + 4];
            ulonglong2 b0 = *(const ulonglong2*)&Bs[k * CO2 + tc * 4];
            FMA2(acc2[0][0], aa.x, b0.x); FMA2(acc2[0][1], aa.x, b0.y);
            FMA2(acc2[1][0], aa.y, b0.x); FMA2(acc2[1][1], aa.y, b0.y);
            FMA2(acc2[2][0], ab.x, b0.x); FMA2(acc2[2][1], ab.x, b0.y);
            FMA2(acc2[3][0], ab.y, b0.x); FMA2(acc2[3][1], ab.y, b0.y);
            if (NG == 2) {
                ulonglong2 b1v = *(const ulonglong2*)&Bs[k * CO2 + 64 + tc * 4];
                FMA2(acc2[0][2], aa.x, b1v.x); FMA2(acc2[0][3], aa.x, b1v.y);
                FMA2(acc2[1][2], aa.y, b1v.x); FMA2(acc2[1][3], aa.y, b1v.y);
                FMA2(acc2[2][2], ab.x, b1v.x); FMA2(acc2[2][3], ab.x, b1v.y);
                FMA2(acc2[3][2], ab.y, b1v.x); FMA2(acc2[3][3], ab.y, b1v.y);
            }
        }
        __syncthreads();
    }

    // ---- final epilogue ----
    {
        float bb[4 * NG];
#pragma unroll
        for (int g = 0; g < NG; ++g)
#pragma unroll
            for (int e = 0; e < 4; ++e)
                bb[g * 4 + e] = __ldg(&b2[g * 64 + tc * 4 + e]);
#pragma unroll
        for (int i = 0; i < 4; ++i) {
            long long row = rowBase + tr * 4 + i;
            if (row >= Nrows) continue;
#pragma unroll
            for (int g = 0; g < NG; ++g) {
                uint32_t l0, h0, l1, h1;
                UNPK(l0, h0, acc2[i][g * 2 + 0]);
                UNPK(l1, h1, acc2[i][g * 2 + 1]);
                float4 o;
                o.x = __uint_as_float(l0) + bb[g * 4 + 0];
                o.y = __uint_as_float(h0) + bb[g * 4 + 1];
                o.z = __uint_as_float(l1) + bb[g * 4 + 2];
                o.w = __uint_as_float(h1) + bb[g * 4 + 3];
                if (RELU2) {
                    o.x = fmaxf(o.x, 0.f); o.y = fmaxf(o.y, 0.f);
                    o.z = fmaxf(o.z, 0.f); o.w = fmaxf(o.w, 0.f);
                }
                *(float4*)(Out + row * CO2 + g * 64 + tc * 4) = o;
            }
        }
    }
}

// ---------------------------------------------------------------------------
extern "C" void kernel_launch(void* const* d_in, const int* in_sizes, int n_in,
                              void* d_out, int out_size) {
    const float* x  = (const float*)d_in[0];
    const void*  ei = d_in[1];
    const float* W1 = (const float*)d_in[2];
    const float* b1 = (const float*)d_in[3];
    const float* W2 = (const float*)d_in[4];
    const float* b2 = (const float*)d_in[5];
    const float* W3 = (const float*)d_in[6];
    const float* b3 = (const float*)d_in[7];
    const float* W4 = (const float*)d_in[8];
    const float* b4 = (const float*)d_in[9];

    const int N = in_sizes[0] / CIN;
    const int E = in_sizes[1] / 2;

    float *h1pre, *h, *h2pre;
    cudaGetSymbolAddress((void**)&h1pre, g_h1pre);
    cudaGetSymbolAddress((void**)&h,     g_h);
    cudaGetSymbolAddress((void**)&h2pre, g_h2pre);
    int *deg, *offs, *cursor, *csr, *part;
    cudaGetSymbolAddress((void**)&deg,    g_deg);
    cudaGetSymbolAddress((void**)&offs,   g_offs);
    cudaGetSymbolAddress((void**)&cursor, g_cursor);
    cudaGetSymbolAddress((void**)&csr,    g_csr);
    cudaGetSymbolAddress((void**)&part,   g_part);

    float* out = (float*)d_out;
    const int rtiles      = (N + 63) / 64;
    const int edge_blocks = (E + 255) / 256;
    const int scan_blocks = (N + SCAN_BS - 1) / SCAN_BS;
    const int g64_blocks  = (N * 16 + 255) / 256;
    const int g128_blocks = (N * 32 + 255) / 256;

    // Aliased As/T1 buffer (128 x 132 floats) + W double buffer -> ~100 KB.
    const int smem_mlp = (128 * 132 + 2 * 32 * 128) * 4;
    cudaFuncSetAttribute(mlp_fused_kernel<CIN,  CHID, 1>,
                         cudaFuncAttributeMaxDynamicSharedMemorySize, smem_mlp);
    cudaFuncSetAttribute(mlp_fused_kernel<CHID, CIN,  0>,
                         cudaFuncAttributeMaxDynamicSharedMemorySize, smem_mlp);

    // ---- CSR build (5 launches) ----
    detect_zero_kernel<<<(N + 255) / 256, 256>>>((const unsigned*)ei, deg, N);
    hist_kernel<<<edge_blocks, 256>>>(ei, deg, E);
    scan1_kernel<<<scan_blocks, SCAN_BS>>>(deg, offs, part, N);
    scan23_kernel<<<scan_blocks, SCAN_BS>>>(offs, cursor, part, scan_blocks, N);
    fill_kernel<<<edge_blocks, 256>>>(ei, cursor, csr, E);

    // ---- Layer 1 ----
    gather64_kernel<<<g64_blocks, 256>>>(x, offs, csr, h1pre, N);
    mlp_fused_kernel<CIN,  CHID, 1><<<rtiles, 256, smem_mlp>>>(h1pre, W1, b1, W2, b2, h, N);

    // ---- Layer 2 ----
    gather128_kernel<<<g128_blocks, 256>>>(h, offs, csr, h2pre, N);
    mlp_fused_kernel<CHID, CIN,  0><<<rtiles, 256, smem_mlp>>>(h2pre, W3, b3, W4, b4, out, N);
}